// round 6
// baseline (speedup 1.0000x reference)
#include <cuda_runtime.h>
#include <cuda_bf16.h>
#include <math.h>

#define B_   4
#define C64  64
#define H_   256
#define W_   256
#define HW_  65536
#define PW_  128
#define PHW_ 16384

typedef unsigned long long ull;

// ---------------- f32x2 packed helpers ----------------
__device__ __forceinline__ ull pk2(float lo, float hi) {
    ull r;
    asm("mov.b64 %0, {%1, %2};" : "=l"(r) : "f"(lo), "f"(hi));
    return r;
}
__device__ __forceinline__ void fma2(ull& d, ull a, ull b) {
    asm("fma.rn.f32x2 %0, %1, %2, %0;" : "+l"(d) : "l"(a), "l"(b));
}
__device__ __forceinline__ float2 unpk2(ull v) {
    float lo, hi;
    asm("mov.b64 {%0, %1}, %2;" : "=f"(lo), "=f"(hi) : "l"(v));
    return make_float2(lo, hi);
}

// ---------------- scratch ----------------
__device__ float g_xh[B_*C64*HW_];
__device__ float g_yh[B_*C64*HW_];
__device__ float g_px[B_*C64*PHW_];
__device__ float g_py[B_*C64*PHW_];
__device__ float g_Cxy[B_*4096];
__device__ float g_Pxx[B_*4096];
__device__ float g_Pyy[B_*4096];
__device__ float g_Pxy[B_*4096];
__device__ float g_M1[B_*4096];
__device__ float g_M2[B_*4096];

// ---------------- zero kernels (split 3-way so k1 is stream launch index 3 for ncu) ----
__global__ void kz_a() {
    int i = blockIdx.x * 256 + threadIdx.x;
    if (i < B_*4096) { g_Cxy[i] = 0.f; g_Pxx[i] = 0.f; }
}
__global__ void kz_b() {
    int i = blockIdx.x * 256 + threadIdx.x;
    if (i < B_*4096) g_Pyy[i] = 0.f;
}
__global__ void kz_c() {
    int i = blockIdx.x * 256 + threadIdx.x;
    if (i < B_*4096) g_Pxy[i] = 0.f;
}

// ---------------- K1: depthwise conv + avgpool, 64x64 tile, 4x4 per thread ----------------
template<int K>
__device__ __forceinline__ void conv4(const float (*s)[72], const float2* __restrict__ wps,
                                      int rq, int cq, float4 out[4]) {
    const int hoff = 4 - K/2;
    const int base_r = 4*rq + 3 - K/2;
    const int xb = 4*cq;

    ull accA[4], accB[4];
#pragma unroll
    for (int c = 0; c < 4; ++c) { accA[c] = 0ULL; accB[c] = 0ULL; }

    float P[12], Cr[12];
    {
        float4 a = *(const float4*)&s[base_r][xb];
        float4 b = *(const float4*)&s[base_r][xb+4];
        float4 c = *(const float4*)&s[base_r][xb+8];
        P[0]=a.x;P[1]=a.y;P[2]=a.z;P[3]=a.w;P[4]=b.x;P[5]=b.y;P[6]=b.z;P[7]=b.w;
        P[8]=c.x;P[9]=c.y;P[10]=c.z;P[11]=c.w;
    }
#pragma unroll
    for (int m = 1; m <= K+2; ++m) {
        {
            float4 a = *(const float4*)&s[base_r+m][xb];
            float4 b = *(const float4*)&s[base_r+m][xb+4];
            float4 c = *(const float4*)&s[base_r+m][xb+8];
            Cr[0]=a.x;Cr[1]=a.y;Cr[2]=a.z;Cr[3]=a.w;Cr[4]=b.x;Cr[5]=b.y;Cr[6]=b.z;Cr[7]=b.w;
            Cr[8]=c.x;Cr[9]=c.y;Cr[10]=c.z;Cr[11]=c.w;
        }
        ull pv[K+3];
#pragma unroll
        for (int i = 0; i < K+3; ++i) pv[i] = pk2(P[hoff+i], Cr[hoff+i]);
        const int mp = m - 1;
        if (mp <= K-1) {
#pragma unroll
            for (int dx = 0; dx < K; ++dx) {
                ull wp = *(const ull*)&wps[mp*K + dx];
#pragma unroll
                for (int c = 0; c < 4; ++c) fma2(accA[c], wp, pv[dx+c]);
            }
        }
        if (mp >= 2) {
#pragma unroll
            for (int dx = 0; dx < K; ++dx) {
                ull wp = *(const ull*)&wps[(mp-2)*K + dx];
#pragma unroll
                for (int c = 0; c < 4; ++c) fma2(accB[c], wp, pv[dx+c]);
            }
        }
#pragma unroll
        for (int i = 0; i < 12; ++i) P[i] = Cr[i];
    }
    float2 a0 = unpk2(accA[0]), a1 = unpk2(accA[1]), a2 = unpk2(accA[2]), a3 = unpk2(accA[3]);
    float2 b0 = unpk2(accB[0]), b1 = unpk2(accB[1]), b2 = unpk2(accB[2]), b3 = unpk2(accB[3]);
    out[0] = make_float4(a0.x, a1.x, a2.x, a3.x);
    out[1] = make_float4(a0.y, a1.y, a2.y, a3.y);
    out[2] = make_float4(b0.x, b1.x, b2.x, b3.x);
    out[3] = make_float4(b0.y, b1.y, b2.y, b3.y);
}

__global__ __launch_bounds__(256)
void k1_dwconv_pool(const float* __restrict__ x, const float* __restrict__ y,
                    const float* __restrict__ h1w3, const float* __restrict__ h1w5,
                    const float* __restrict__ h1w7,
                    const float* __restrict__ h2w3, const float* __restrict__ h2w5,
                    const float* __restrict__ h2w7) {
    __shared__ float s[70][72];
    __shared__ float2 wps[49];

    const int c = blockIdx.y;
    const int z = blockIdx.z;
    const int b = z >> 1;
    const int which = z & 1;
    const int ty0 = (blockIdx.x >> 2) * 64;
    const int tx0 = (blockIdx.x & 3) * 64;
    const int tid = threadIdx.x;

    const float* src = which ? y : x;
    const float* w3  = which ? h2w3 : h1w3;
    const float* w5  = which ? h2w5 : h1w5;
    const float* w7  = which ? h2w7 : h1w7;
    float* dst  = which ? g_yh : g_xh;
    float* pdst = which ? g_py : g_px;

    const float* wp; int wn;
    if (c < 32)      { wp = w3 + c*9;        wn = 9;  }
    else if (c < 48) { wp = w5 + (c-32)*25;  wn = 25; }
    else             { wp = w7 + (c-48)*49;  wn = 49; }
    if (tid < wn) { float w = wp[tid]; wps[tid] = make_float2(w, w); }

    const float* base = src + (size_t)(b*C64 + c) * HW_;
    for (int i = tid; i < 70*18; i += 256) {
        int r = i / 18, q = i - r*18;
        int gy = ty0 - 3 + r, gx = tx0 - 4 + q*4;
        float4 v = make_float4(0.f, 0.f, 0.f, 0.f);
        if ((unsigned)gy < 256u && (unsigned)gx <= 252u)
            v = *(const float4*)&base[gy*W_ + gx];
        *(float4*)&s[r][q*4] = v;
    }
    __syncthreads();

    const int rq = tid >> 4;
    const int cq = tid & 15;
    float4 o[4];
    if (c < 32)      conv4<3>(s, wps, rq, cq, o);
    else if (c < 48) conv4<5>(s, wps, rq, cq, o);
    else             conv4<7>(s, wps, rq, cq, o);

    float* dplane = dst + (size_t)(b*C64 + c) * HW_;
#pragma unroll
    for (int t = 0; t < 4; ++t)
        *(float4*)&dplane[(ty0 + 4*rq + t)*W_ + tx0 + 4*cq] = o[t];

    {
        const int pr  = tid >> 3;
        const int pc4 = (tid & 7) * 4;
        float4 pv;
        float* e = &pv.x;
#pragma unroll
        for (int d = 0; d < 4; ++d) {
            int pc = pc4 + d;
            e[d] = 0.25f * (s[2*pr+3][2*pc+4] + s[2*pr+3][2*pc+5] +
                            s[2*pr+4][2*pc+4] + s[2*pr+4][2*pc+5]);
        }
        float* pplane = pdst + (size_t)(b*C64 + c) * PHW_;
        *(float4*)&pplane[(ty0/2 + pr)*PW_ + tx0/2 + pc4] = pv;
    }
}

// ---------------- K2 merged: Pxx, Pyy, Pxy in one pass ----------------
__global__ __launch_bounds__(256, 1)
void k2_moments() {
    extern __shared__ float sm[];
    float* sx = sm;               // [64][130]
    float* sy = sm + 64*130;
    const int b = blockIdx.y;
    const int tid = threadIdx.x;
    const int q = tid >> 4;
    const int l = tid & 15;
    ull axx[16], ayy[16], axy[16];
#pragma unroll
    for (int u = 0; u < 16; ++u) { axx[u] = 0ULL; ayy[u] = 0ULL; axy[u] = 0ULL; }

    for (int chunk = blockIdx.x; chunk < PHW_/128; chunk += gridDim.x) {
        const int n0 = chunk * 128;
        __syncthreads();
        for (int li = tid; li < 2048; li += 256) {
            int cc = li >> 5, t4 = (li & 31) * 4;
            size_t go = ((size_t)(b*C64 + cc) << 14) + n0 + t4;
            float4 vx = *(const float4*)&g_px[go];
            float4 vy = *(const float4*)&g_py[go];
            *(float2*)&sx[cc*130 + t4]     = make_float2(vx.x, vx.y);
            *(float2*)&sx[cc*130 + t4 + 2] = make_float2(vx.z, vx.w);
            *(float2*)&sy[cc*130 + t4]     = make_float2(vy.x, vy.y);
            *(float2*)&sy[cc*130 + t4 + 2] = make_float2(vy.z, vy.w);
        }
        __syncthreads();
#pragma unroll 2
        for (int t = 0; t < 128; t += 2) {
            ull ax[4], bx[4], ay[4], by[4];
#pragma unroll
            for (int u = 0; u < 4; ++u) {
                ax[u] = *(const ull*)&sx[(q + 16*u)*130 + t];
                bx[u] = *(const ull*)&sx[(l + 16*u)*130 + t];
                ay[u] = *(const ull*)&sy[(q + 16*u)*130 + t];
                by[u] = *(const ull*)&sy[(l + 16*u)*130 + t];
            }
#pragma unroll
            for (int u = 0; u < 4; ++u)
#pragma unroll
                for (int v = 0; v < 4; ++v) {
                    fma2(axx[u*4+v], ax[u], bx[v]);
                    fma2(ayy[u*4+v], ay[u], by[v]);
                    fma2(axy[u*4+v], ax[u], by[v]);
                }
        }
    }
#pragma unroll
    for (int u = 0; u < 4; ++u)
#pragma unroll
        for (int v = 0; v < 4; ++v) {
            float2 fx = unpk2(axx[u*4+v]);
            float2 fy = unpk2(ayy[u*4+v]);
            float2 fz = unpk2(axy[u*4+v]);
            int o = b*4096 + (q+16*u)*64 + (l+16*v);
            atomicAdd(&g_Pxx[o], fx.x + fx.y);
            atomicAdd(&g_Pyy[o], fy.x + fy.y);
            atomicAdd(&g_Pxy[o], fz.x + fz.y);
        }
}

// ---------------- K3: Cxy = x_h @ y_h^T, 8x4 register tiles (crossbar relief) ----------------
__global__ __launch_bounds__(256, 2)
void k3_cxy() {
    extern __shared__ float sm[];
    float* sx = sm;               // [64][130]
    float* sy = sm + 64*130;
    const int b = blockIdx.y;
    const int tid = threadIdx.x;
    const int th = tid >> 7;          // t-half: 0 -> t in [0,64), 1 -> [64,128)
    const int q  = (tid >> 4) & 7;    // i rows {q + 8u}, u=0..7
    const int l  = tid & 15;          // j rows {l + 16v}, v=0..3
    ull acc[32];
#pragma unroll
    for (int u = 0; u < 32; ++u) acc[u] = 0ULL;

    for (int chunk = blockIdx.x; chunk < HW_/128; chunk += gridDim.x) {
        const int n0 = chunk * 128;
        __syncthreads();
        for (int li = tid; li < 2048; li += 256) {
            int cc = li >> 5, t4 = (li & 31) * 4;
            size_t go = ((size_t)(b*C64 + cc) << 16) + n0 + t4;
            float4 vx = *(const float4*)&g_xh[go];
            float4 vy = *(const float4*)&g_yh[go];
            *(float2*)&sx[cc*130 + t4]     = make_float2(vx.x, vx.y);
            *(float2*)&sx[cc*130 + t4 + 2] = make_float2(vx.z, vx.w);
            *(float2*)&sy[cc*130 + t4]     = make_float2(vy.x, vy.y);
            *(float2*)&sy[cc*130 + t4 + 2] = make_float2(vy.z, vy.w);
        }
        __syncthreads();
        const int tbase = th * 64;
#pragma unroll 2
        for (int tt = 0; tt < 64; tt += 2) {
            const int t = tbase + tt;
            ull a[8], bb[4];
#pragma unroll
            for (int u = 0; u < 8; ++u)
                a[u] = *(const ull*)&sx[(q + 8*u)*130 + t];
#pragma unroll
            for (int v = 0; v < 4; ++v)
                bb[v] = *(const ull*)&sy[(l + 16*v)*130 + t];
#pragma unroll
            for (int u = 0; u < 8; ++u)
#pragma unroll
                for (int v = 0; v < 4; ++v)
                    fma2(acc[u*4+v], a[u], bb[v]);
        }
    }
#pragma unroll
    for (int u = 0; u < 8; ++u)
#pragma unroll
        for (int v = 0; v < 4; ++v) {
            float2 f = unpk2(acc[u*4+v]);
            atomicAdd(&g_Cxy[b*4096 + (q+8*u)*64 + (l+16*v)], f.x + f.y);
        }
}

// ---------------- K4: per-batch finalize -> M1, M2 ----------------
__global__ void k4_finalize(const float* __restrict__ qh, const float* __restrict__ kh,
                            const float* __restrict__ vh, const float* __restrict__ ql,
                            const float* __restrict__ kl, const float* __restrict__ vl,
                            const float* __restrict__ proj,
                            const float* __restrict__ w1, const float* __restrict__ w2,
                            const float* __restrict__ temp) {
    __shared__ float T2[4096];
    __shared__ float S[4096];
    __shared__ float pooled[64], hidden[16], ha[64], nq2[64], nk2[64];
    __shared__ float A[512];
    __shared__ float psum[256];

    const int b = blockIdx.x, tid = threadIdx.x;
    const float* Cxy = g_Cxy + b*4096;
    const float* Pxx = g_Pxx + b*4096;
    const float* Pyy = g_Pyy + b*4096;
    const float* Pxy = g_Pxy + b*4096;

    {
        int c = tid & 63, qq = tid >> 6;
        float acc = 0.f;
        for (int i = qq*16; i < qq*16 + 16; ++i) {
            const float* cr = Cxy + i*64;
            const float* kr = kh + c*64;
            float s0=0,s1=0,s2=0,s3=0;
            for (int j = 0; j < 64; j += 4) {
                s0 += cr[j  ]*kr[j  ]; s1 += cr[j+1]*kr[j+1];
                s2 += cr[j+2]*kr[j+2]; s3 += cr[j+3]*kr[j+3];
            }
            acc += qh[c*64+i]*(s0+s1+s2+s3);
        }
        psum[tid] = acc;
        __syncthreads();
        if (tid < 64) pooled[tid] = (psum[tid]+psum[tid+64]+psum[tid+128]+psum[tid+192]) * (1.0f/(float)HW_);
        __syncthreads();
    }
    if (tid < 16) {
        float a = 0.f;
        for (int cc = 0; cc < 64; ++cc) a += w1[tid*64+cc]*pooled[cc];
        hidden[tid] = fmaxf(a, 0.f);
    }
    __syncthreads();
    if (tid < 64) {
        float a = 0.f;
        for (int j = 0; j < 16; ++j) a += w2[tid*16+j]*hidden[j];
        ha[tid] = tanhf(a);
    }
    __syncthreads();

    {   // T2 = ql @ Pxy
        int c = tid >> 2, j0 = (tid & 3)*16;
        float acc[16];
#pragma unroll
        for (int v = 0; v < 16; ++v) acc[v] = 0.f;
        for (int i = 0; i < 64; ++i) {
            float a = ql[c*64+i];
            const float* pr = Pxy + i*64 + j0;
#pragma unroll
            for (int v = 0; v < 16; ++v) acc[v] += a*pr[v];
        }
#pragma unroll
        for (int v = 0; v < 16; ++v) T2[c*64+j0+v] = acc[v];
    }
    __syncthreads();
    {   // S = T2 @ kl^T
        int c = tid >> 2, d0 = (tid & 3)*16;
        float acc[16];
#pragma unroll
        for (int v = 0; v < 16; ++v) acc[v] = 0.f;
        for (int j = 0; j < 64; ++j) {
            float a = T2[c*64+j];
#pragma unroll
            for (int v = 0; v < 16; ++v) acc[v] += a*kl[(d0+v)*64+j];
        }
#pragma unroll
        for (int v = 0; v < 16; ++v) S[c*64+d0+v] = acc[v];
    }
    __syncthreads();
    {   // T2 = ql @ Pxx -> nq2
        int c = tid >> 2, j0 = (tid & 3)*16;
        float acc[16];
#pragma unroll
        for (int v = 0; v < 16; ++v) acc[v] = 0.f;
        for (int i = 0; i < 64; ++i) {
            float a = ql[c*64+i];
            const float* pr = Pxx + i*64 + j0;
#pragma unroll
            for (int v = 0; v < 16; ++v) acc[v] += a*pr[v];
        }
#pragma unroll
        for (int v = 0; v < 16; ++v) T2[c*64+j0+v] = acc[v];
    }
    __syncthreads();
    if (tid < 64) {
        float a = 0.f;
        for (int j = 0; j < 64; ++j) a += T2[tid*64+j]*ql[tid*64+j];
        nq2[tid] = a;
    }
    __syncthreads();
    {   // T2 = kl @ Pyy -> nk2
        int c = tid >> 2, j0 = (tid & 3)*16;
        float acc[16];
#pragma unroll
        for (int v = 0; v < 16; ++v) acc[v] = 0.f;
        for (int i = 0; i < 64; ++i) {
            float a = kl[c*64+i];
            const float* pr = Pyy + i*64 + j0;
#pragma unroll
            for (int v = 0; v < 16; ++v) acc[v] += a*pr[v];
        }
#pragma unroll
        for (int v = 0; v < 16; ++v) T2[c*64+j0+v] = acc[v];
    }
    __syncthreads();
    if (tid < 64) {
        float a = 0.f;
        for (int j = 0; j < 64; ++j) a += T2[tid*64+j]*kl[tid*64+j];
        nk2[tid] = a;
    }
    __syncthreads();

    if (tid < 64) {
        int c = tid, h = c >> 3;
        float dq = fmaxf(sqrtf(nq2[c]), 1e-12f);
        float tt = temp[h];
        float v[8]; float mx = -1e30f;
#pragma unroll
        for (int dd = 0; dd < 8; ++dd) {
            int d = h*8 + dd;
            float dk = fmaxf(sqrtf(nk2[d]), 1e-12f);
            v[dd] = S[c*64+d] / (dq*dk) * tt;
            mx = fmaxf(mx, v[dd]);
        }
        float sum = 0.f;
#pragma unroll
        for (int dd = 0; dd < 8; ++dd) { v[dd] = expf(v[dd]-mx); sum += v[dd]; }
        float inv = 1.f/sum;
#pragma unroll
        for (int dd = 0; dd < 8; ++dd) A[c*8+dd] = v[dd]*inv;
    }
    __syncthreads();

    {   // S := blockdiag(A) @ vl ; T2 := diag(ha) @ vh
        int c = tid >> 2, i0 = (tid & 3)*16, h = c >> 3;
        float acc[16];
#pragma unroll
        for (int v = 0; v < 16; ++v) acc[v] = 0.f;
#pragma unroll
        for (int dd = 0; dd < 8; ++dd) {
            float a = A[c*8+dd];
            const float* vr = vl + (h*8+dd)*64 + i0;
#pragma unroll
            for (int v = 0; v < 16; ++v) acc[v] += a*vr[v];
        }
#pragma unroll
        for (int v = 0; v < 16; ++v) S[c*64+i0+v] = acc[v];
        float hac = ha[c];
#pragma unroll
        for (int v = 0; v < 16; ++v) T2[c*64+i0+v] = hac*vh[c*64+i0+v];
    }
    __syncthreads();

    {   // M1 = proj @ T2 ; M2 = proj @ S
        int o = tid >> 2, i0 = (tid & 3)*16;
        float a1[16], a2[16];
#pragma unroll
        for (int v = 0; v < 16; ++v) { a1[v] = 0.f; a2[v] = 0.f; }
        for (int c = 0; c < 64; ++c) {
            float p = proj[o*64+c];
            const float* u  = T2 + c*64 + i0;
            const float* bm = S  + c*64 + i0;
#pragma unroll
            for (int v = 0; v < 16; ++v) { a1[v] += p*u[v]; a2[v] += p*bm[v]; }
        }
#pragma unroll
        for (int v = 0; v < 16; ++v) {
            g_M1[b*4096 + o*64 + i0 + v] = a1[v];
            g_M2[b*4096 + o*64 + i0 + v] = a2[v];
        }
    }
}

// ---------------- K5: out = M1 @ x_h + M2 @ y, 8-row x 4-col tiles, uniform A ----------------
__global__ __launch_bounds__(256, 2)
void k5_final(const float* __restrict__ y, float* __restrict__ out) {
    extern __shared__ float sm[];
    float* m1 = sm;                 // [64][65]
    float* m2 = sm + 64*65;
    float* sa = sm + 2*64*65;       // x_h chunk [64][132]
    float* sb = sa + 64*132;        // y   chunk [64][132]

    const int b = blockIdx.y;
    const int tid = threadIdx.x;
    const int n0 = blockIdx.x * 128;

    for (int li = tid; li < 4096; li += 256) {
        int o = li >> 6, k = li & 63;
        m1[o*65+k] = g_M1[b*4096 + li];
        m2[o*65+k] = g_M2[b*4096 + li];
    }
    for (int li = tid; li < 2048; li += 256) {
        int cc = li >> 5, t4 = (li & 31) * 4;
        size_t go = ((size_t)(b*C64 + cc) << 16) + n0 + t4;
        *(float4*)&sa[cc*132 + t4] = *(const float4*)&g_xh[go];
        *(float4*)&sb[cc*132 + t4] = *(const float4*)&y[go];
    }
    __syncthreads();

    const int o0 = (tid >> 5) * 8;     // 8 output rows, uniform within warp
    const int l  = tid & 31;           // cols {2l, 2l+64}
    ull acc[16];                       // [u][v]: u=0..7 rows, v=0..1 col-pairs
#pragma unroll
    for (int u = 0; u < 16; ++u) acc[u] = 0ULL;

#pragma unroll 2
    for (int k = 0; k < 64; ++k) {
        ull bx[2], by[2];
#pragma unroll
        for (int v = 0; v < 2; ++v) {
            bx[v] = *(const ull*)&sa[k*132 + 2*l + 64*v];
            by[v] = *(const ull*)&sb[k*132 + 2*l + 64*v];
        }
#pragma unroll
        for (int u = 0; u < 8; ++u) {
            float a1 = m1[(o0+u)*65 + k];
            float a2 = m2[(o0+u)*65 + k];
            ull a1p = pk2(a1, a1);
            ull a2p = pk2(a2, a2);
            fma2(acc[u*2+0], a1p, bx[0]);
            fma2(acc[u*2+1], a1p, bx[1]);
            fma2(acc[u*2+0], a2p, by[0]);
            fma2(acc[u*2+1], a2p, by[1]);
        }
    }
#pragma unroll
    for (int u = 0; u < 8; ++u) {
        float* op = out + (size_t)(b*C64 + o0 + u)*HW_ + n0 + 2*l;
        float2 f0 = unpk2(acc[u*2+0]);
        float2 f1 = unpk2(acc[u*2+1]);
        *(float2*)(op)      = f0;
        *(float2*)(op + 64) = f1;
    }
}

// ---------------- launcher ----------------
extern "C" void kernel_launch(void* const* d_in, const int* in_sizes, int n_in,
                              void* d_out, int out_size) {
    (void)in_sizes; (void)n_in; (void)out_size;
    const float* x      = (const float*)d_in[0];
    const float* y      = (const float*)d_in[1];
    const float* h1w3   = (const float*)d_in[2];
    const float* h1w5   = (const float*)d_in[3];
    const float* h1w7   = (const float*)d_in[4];
    const float* h2w3   = (const float*)d_in[5];
    const float* h2w5   = (const float*)d_in[6];
    const float* h2w7   = (const float*)d_in[7];
    const float* qh_w   = (const float*)d_in[8];
    const float* kh_w   = (const float*)d_in[9];
    const float* vh_w   = (const float*)d_in[10];
    const float* ql_w   = (const float*)d_in[11];
    const float* kl_w   = (const float*)d_in[12];
    const float* vl_w   = (const float*)d_in[13];
    const float* proj_w = (const float*)d_in[14];
    const float* w1     = (const float*)d_in[15];
    const float* w2     = (const float*)d_in[16];
    const float* temp   = (const float*)d_in[17];
    float* out = (float*)d_out;

    const int SMEM_GEMM = 2*64*130*4;               // 66560
    const int SMEM5     = (2*64*65 + 2*64*132)*4;   // 100864
    cudaFuncSetAttribute(k3_cxy,     cudaFuncAttributeMaxDynamicSharedMemorySize, SMEM_GEMM);
    cudaFuncSetAttribute(k2_moments, cudaFuncAttributeMaxDynamicSharedMemorySize, SMEM_GEMM);
    cudaFuncSetAttribute(k5_final,   cudaFuncAttributeMaxDynamicSharedMemorySize, SMEM5);

    // launch order chosen so k1 is stream launch index 3 (ncu capture slot)
    kz_a<<<64, 256>>>();
    kz_b<<<64, 256>>>();
    kz_c<<<64, 256>>>();
    k1_dwconv_pool<<<dim3(16, 64, 8), 256>>>(x, y, h1w3, h1w5, h1w7, h2w3, h2w5, h2w7);
    k2_moments<<<dim3(37, B_), 256, SMEM_GEMM>>>();
    k3_cxy<<<dim3(74, B_), 256, SMEM_GEMM>>>();
    k4_finalize<<<B_, 256>>>(qh_w, kh_w, vh_w, ql_w, kl_w, vl_w, proj_w, w1, w2, temp);
    k5_final<<<dim3(HW_/128, B_), 256, SMEM5>>>(y, out);
}

// round 9
// speedup vs baseline: 1.0945x; 1.0945x over previous
#include <cuda_runtime.h>
#include <cuda_bf16.h>
#include <math.h>

#define B_   4
#define C64  64
#define H_   256
#define W_   256
#define HW_  65536
#define PW_  128
#define PHW_ 16384

typedef unsigned long long ull;

// ---------------- f32x2 packed helpers ----------------
__device__ __forceinline__ ull pk2(float lo, float hi) {
    ull r;
    asm("mov.b64 %0, {%1, %2};" : "=l"(r) : "f"(lo), "f"(hi));
    return r;
}
__device__ __forceinline__ void fma2(ull& d, ull a, ull b) {
    asm("fma.rn.f32x2 %0, %1, %2, %0;" : "+l"(d) : "l"(a), "l"(b));
}
__device__ __forceinline__ float2 unpk2(ull v) {
    float lo, hi;
    asm("mov.b64 {%0, %1}, %2;" : "=f"(lo), "=f"(hi) : "l"(v));
    return make_float2(lo, hi);
}

// ---------------- scratch ----------------
__device__ float g_xh[B_*C64*HW_];
__device__ float g_yh[B_*C64*HW_];
__device__ float g_px[B_*C64*PHW_];
__device__ float g_py[B_*C64*PHW_];
__device__ float g_Cxy[B_*4096];
__device__ float g_Pxx[B_*4096];
__device__ float g_Pyy[B_*4096];
__device__ float g_Pxy[B_*4096];
__device__ float g_M1[B_*4096];
__device__ float g_M2[B_*4096];

// ---------------- zero kernels (split so merged k2 lands at ncu slot 3) ----------------
__global__ void kz_a() {
    int i = blockIdx.x * 256 + threadIdx.x;
    if (i < B_*4096) { g_Cxy[i] = 0.f; g_Pxx[i] = 0.f; }
}
__global__ void kz_b() {
    int i = blockIdx.x * 256 + threadIdx.x;
    if (i < B_*4096) { g_Pyy[i] = 0.f; g_Pxy[i] = 0.f; }
}

// ---------------- K1: depthwise conv + avgpool, 64x64 tile, 4x4 per thread (R6 measured) --
template<int K>
__device__ __forceinline__ void conv4(const float (*s)[72], const float2* __restrict__ wps,
                                      int rq, int cq, float4 out[4]) {
    const int hoff = 4 - K/2;
    const int base_r = 4*rq + 3 - K/2;
    const int xb = 4*cq;

    ull accA[4], accB[4];
#pragma unroll
    for (int c = 0; c < 4; ++c) { accA[c] = 0ULL; accB[c] = 0ULL; }

    float P[12], Cr[12];
    {
        float4 a = *(const float4*)&s[base_r][xb];
        float4 b = *(const float4*)&s[base_r][xb+4];
        float4 c = *(const float4*)&s[base_r][xb+8];
        P[0]=a.x;P[1]=a.y;P[2]=a.z;P[3]=a.w;P[4]=b.x;P[5]=b.y;P[6]=b.z;P[7]=b.w;
        P[8]=c.x;P[9]=c.y;P[10]=c.z;P[11]=c.w;
    }
#pragma unroll
    for (int m = 1; m <= K+2; ++m) {
        {
            float4 a = *(const float4*)&s[base_r+m][xb];
            float4 b = *(const float4*)&s[base_r+m][xb+4];
            float4 c = *(const float4*)&s[base_r+m][xb+8];
            Cr[0]=a.x;Cr[1]=a.y;Cr[2]=a.z;Cr[3]=a.w;Cr[4]=b.x;Cr[5]=b.y;Cr[6]=b.z;Cr[7]=b.w;
            Cr[8]=c.x;Cr[9]=c.y;Cr[10]=c.z;Cr[11]=c.w;
        }
        ull pv[K+3];
#pragma unroll
        for (int i = 0; i < K+3; ++i) pv[i] = pk2(P[hoff+i], Cr[hoff+i]);
        const int mp = m - 1;
        if (mp <= K-1) {
#pragma unroll
            for (int dx = 0; dx < K; ++dx) {
                ull wp = *(const ull*)&wps[mp*K + dx];
#pragma unroll
                for (int c = 0; c < 4; ++c) fma2(accA[c], wp, pv[dx+c]);
            }
        }
        if (mp >= 2) {
#pragma unroll
            for (int dx = 0; dx < K; ++dx) {
                ull wp = *(const ull*)&wps[(mp-2)*K + dx];
#pragma unroll
                for (int c = 0; c < 4; ++c) fma2(accB[c], wp, pv[dx+c]);
            }
        }
#pragma unroll
        for (int i = 0; i < 12; ++i) P[i] = Cr[i];
    }
    float2 a0 = unpk2(accA[0]), a1 = unpk2(accA[1]), a2 = unpk2(accA[2]), a3 = unpk2(accA[3]);
    float2 b0 = unpk2(accB[0]), b1 = unpk2(accB[1]), b2 = unpk2(accB[2]), b3 = unpk2(accB[3]);
    out[0] = make_float4(a0.x, a1.x, a2.x, a3.x);
    out[1] = make_float4(a0.y, a1.y, a2.y, a3.y);
    out[2] = make_float4(b0.x, b1.x, b2.x, b3.x);
    out[3] = make_float4(b0.y, b1.y, b2.y, b3.y);
}

__global__ __launch_bounds__(256)
void k1_dwconv_pool(const float* __restrict__ x, const float* __restrict__ y,
                    const float* __restrict__ h1w3, const float* __restrict__ h1w5,
                    const float* __restrict__ h1w7,
                    const float* __restrict__ h2w3, const float* __restrict__ h2w5,
                    const float* __restrict__ h2w7) {
    __shared__ float s[70][72];
    __shared__ float2 wps[49];

    const int c = blockIdx.y;
    const int z = blockIdx.z;
    const int b = z >> 1;
    const int which = z & 1;
    const int ty0 = (blockIdx.x >> 2) * 64;
    const int tx0 = (blockIdx.x & 3) * 64;
    const int tid = threadIdx.x;

    const float* src = which ? y : x;
    const float* w3  = which ? h2w3 : h1w3;
    const float* w5  = which ? h2w5 : h1w5;
    const float* w7  = which ? h2w7 : h1w7;
    float* dst  = which ? g_yh : g_xh;
    float* pdst = which ? g_py : g_px;

    const float* wp; int wn;
    if (c < 32)      { wp = w3 + c*9;        wn = 9;  }
    else if (c < 48) { wp = w5 + (c-32)*25;  wn = 25; }
    else             { wp = w7 + (c-48)*49;  wn = 49; }
    if (tid < wn) { float w = wp[tid]; wps[tid] = make_float2(w, w); }

    const float* base = src + (size_t)(b*C64 + c) * HW_;
    for (int i = tid; i < 70*18; i += 256) {
        int r = i / 18, q = i - r*18;
        int gy = ty0 - 3 + r, gx = tx0 - 4 + q*4;
        float4 v = make_float4(0.f, 0.f, 0.f, 0.f);
        if ((unsigned)gy < 256u && (unsigned)gx <= 252u)
            v = *(const float4*)&base[gy*W_ + gx];
        *(float4*)&s[r][q*4] = v;
    }
    __syncthreads();

    const int rq = tid >> 4;
    const int cq = tid & 15;
    float4 o[4];
    if (c < 32)      conv4<3>(s, wps, rq, cq, o);
    else if (c < 48) conv4<5>(s, wps, rq, cq, o);
    else             conv4<7>(s, wps, rq, cq, o);

    float* dplane = dst + (size_t)(b*C64 + c) * HW_;
#pragma unroll
    for (int t = 0; t < 4; ++t)
        *(float4*)&dplane[(ty0 + 4*rq + t)*W_ + tx0 + 4*cq] = o[t];

    {
        const int pr  = tid >> 3;
        const int pc4 = (tid & 7) * 4;
        float4 pv;
        float* e = &pv.x;
#pragma unroll
        for (int d = 0; d < 4; ++d) {
            int pc = pc4 + d;
            e[d] = 0.25f * (s[2*pr+3][2*pc+4] + s[2*pr+3][2*pc+5] +
                            s[2*pr+4][2*pc+4] + s[2*pr+4][2*pc+5]);
        }
        float* pplane = pdst + (size_t)(b*C64 + c) * PHW_;
        *(float4*)&pplane[(ty0/2 + pr)*PW_ + tx0/2 + pc4] = pv;
    }
}

// ---------------- K2 merged: Pxx, Pyy, Pxy in one pass (R5-measured config) ------------
__global__ __launch_bounds__(256, 1)
void k2_moments() {
    extern __shared__ float sm[];
    float* sx = sm;               // [64][130]
    float* sy = sm + 64*130;
    const int b = blockIdx.y;
    const int tid = threadIdx.x;
    const int q = tid >> 4;
    const int l = tid & 15;
    ull axx[16], ayy[16], axy[16];
#pragma unroll
    for (int u = 0; u < 16; ++u) { axx[u] = 0ULL; ayy[u] = 0ULL; axy[u] = 0ULL; }

    for (int chunk = blockIdx.x; chunk < PHW_/128; chunk += gridDim.x) {
        const int n0 = chunk * 128;
        __syncthreads();
        for (int li = tid; li < 2048; li += 256) {
            int cc = li >> 5, t4 = (li & 31) * 4;
            size_t go = ((size_t)(b*C64 + cc) << 14) + n0 + t4;
            float4 vx = *(const float4*)&g_px[go];
            float4 vy = *(const float4*)&g_py[go];
            *(float2*)&sx[cc*130 + t4]     = make_float2(vx.x, vx.y);
            *(float2*)&sx[cc*130 + t4 + 2] = make_float2(vx.z, vx.w);
            *(float2*)&sy[cc*130 + t4]     = make_float2(vy.x, vy.y);
            *(float2*)&sy[cc*130 + t4 + 2] = make_float2(vy.z, vy.w);
        }
        __syncthreads();
#pragma unroll 2
        for (int t = 0; t < 128; t += 2) {
            ull ax[4], bx[4], ay[4], by[4];
#pragma unroll
            for (int u = 0; u < 4; ++u) {
                ax[u] = *(const ull*)&sx[(q + 16*u)*130 + t];
                bx[u] = *(const ull*)&sx[(l + 16*u)*130 + t];
                ay[u] = *(const ull*)&sy[(q + 16*u)*130 + t];
                by[u] = *(const ull*)&sy[(l + 16*u)*130 + t];
            }
#pragma unroll
            for (int u = 0; u < 4; ++u)
#pragma unroll
                for (int v = 0; v < 4; ++v) {
                    fma2(axx[u*4+v], ax[u], bx[v]);
                    fma2(ayy[u*4+v], ay[u], by[v]);
                    fma2(axy[u*4+v], ax[u], by[v]);
                }
        }
    }
#pragma unroll
    for (int u = 0; u < 4; ++u)
#pragma unroll
        for (int v = 0; v < 4; ++v) {
            float2 fx = unpk2(axx[u*4+v]);
            float2 fy = unpk2(ayy[u*4+v]);
            float2 fz = unpk2(axy[u*4+v]);
            int o = b*4096 + (q+16*u)*64 + (l+16*v);
            atomicAdd(&g_Pxx[o], fx.x + fx.y);
            atomicAdd(&g_Pyy[o], fy.x + fy.y);
            atomicAdd(&g_Pxy[o], fz.x + fz.y);
        }
}

// ---------------- K3: Cxy = x_h @ y_h^T, 4x4 tiles, register double-buffered (R5) ------
__global__ __launch_bounds__(256, 2)
void k3_cxy() {
    extern __shared__ float sm[];
    float* sx = sm;               // [64][130]
    float* sy = sm + 64*130;
    const int b = blockIdx.y;
    const int tid = threadIdx.x;
    const int q = tid >> 4;
    const int l = tid & 15;
    const int cc0 = tid >> 5;          // 0..7 (row base for fills)
    const int t4  = (tid & 31) * 4;    // 0..124
    ull acc[16];
#pragma unroll
    for (int u = 0; u < 16; ++u) acc[u] = 0ULL;

    const int NCH = HW_/128;
    float4 rx[4], ry[4];
    int chunk = blockIdx.x;
    {
        int n0 = chunk * 128;
#pragma unroll
        for (int k = 0; k < 4; ++k) {
            size_t go = ((size_t)(b*C64 + cc0 + 8*k) << 16) + n0 + t4;
            rx[k] = *(const float4*)&g_xh[go];
            ry[k] = *(const float4*)&g_yh[go];
        }
    }
    while (true) {
        __syncthreads();
#pragma unroll
        for (int k = 0; k < 4; ++k) {
            int cc = cc0 + 8*k;
            *(float2*)&sx[cc*130 + t4]     = make_float2(rx[k].x, rx[k].y);
            *(float2*)&sx[cc*130 + t4 + 2] = make_float2(rx[k].z, rx[k].w);
            *(float2*)&sy[cc*130 + t4]     = make_float2(ry[k].x, ry[k].y);
            *(float2*)&sy[cc*130 + t4 + 2] = make_float2(ry[k].z, ry[k].w);
        }
        __syncthreads();
        const int next = chunk + gridDim.x;
        if (next < NCH) {
            int n0 = next * 128;
#pragma unroll
            for (int k = 0; k < 4; ++k) {
                size_t go = ((size_t)(b*C64 + cc0 + 8*k) << 16) + n0 + t4;
                rx[k] = *(const float4*)&g_xh[go];
                ry[k] = *(const float4*)&g_yh[go];
            }
        }
#pragma unroll 4
        for (int t = 0; t < 128; t += 2) {
            ull ax[4], by[4];
#pragma unroll
            for (int u = 0; u < 4; ++u) {
                ax[u] = *(const ull*)&sx[(q + 16*u)*130 + t];
                by[u] = *(const ull*)&sy[(l + 16*u)*130 + t];
            }
#pragma unroll
            for (int u = 0; u < 4; ++u)
#pragma unroll
                for (int v = 0; v < 4; ++v)
                    fma2(acc[u*4+v], ax[u], by[v]);
        }
        if (next >= NCH) break;
        chunk = next;
    }
#pragma unroll
    for (int u = 0; u < 4; ++u)
#pragma unroll
        for (int v = 0; v < 4; ++v) {
            float2 f = unpk2(acc[u*4+v]);
            atomicAdd(&g_Cxy[b*4096 + (q+16*u)*64 + (l+16*v)], f.x + f.y);
        }
}

// ---------------- K4: per-batch finalize -> M1, M2 ----------------
__global__ void k4_finalize(const float* __restrict__ qh, const float* __restrict__ kh,
                            const float* __restrict__ vh, const float* __restrict__ ql,
                            const float* __restrict__ kl, const float* __restrict__ vl,
                            const float* __restrict__ proj,
                            const float* __restrict__ w1, const float* __restrict__ w2,
                            const float* __restrict__ temp) {
    __shared__ float T2[4096];
    __shared__ float S[4096];
    __shared__ float pooled[64], hidden[16], ha[64], nq2[64], nk2[64];
    __shared__ float A[512];
    __shared__ float psum[256];

    const int b = blockIdx.x, tid = threadIdx.x;
    const float* Cxy = g_Cxy + b*4096;
    const float* Pxx = g_Pxx + b*4096;
    const float* Pyy = g_Pyy + b*4096;
    const float* Pxy = g_Pxy + b*4096;

    {
        int c = tid & 63, qq = tid >> 6;
        float acc = 0.f;
        for (int i = qq*16; i < qq*16 + 16; ++i) {
            const float* cr = Cxy + i*64;
            const float* kr = kh + c*64;
            float s0=0,s1=0,s2=0,s3=0;
            for (int j = 0; j < 64; j += 4) {
                s0 += cr[j  ]*kr[j  ]; s1 += cr[j+1]*kr[j+1];
                s2 += cr[j+2]*kr[j+2]; s3 += cr[j+3]*kr[j+3];
            }
            acc += qh[c*64+i]*(s0+s1+s2+s3);
        }
        psum[tid] = acc;
        __syncthreads();
        if (tid < 64) pooled[tid] = (psum[tid]+psum[tid+64]+psum[tid+128]+psum[tid+192]) * (1.0f/(float)HW_);
        __syncthreads();
    }
    if (tid < 16) {
        float a = 0.f;
        for (int cc = 0; cc < 64; ++cc) a += w1[tid*64+cc]*pooled[cc];
        hidden[tid] = fmaxf(a, 0.f);
    }
    __syncthreads();
    if (tid < 64) {
        float a = 0.f;
        for (int j = 0; j < 16; ++j) a += w2[tid*16+j]*hidden[j];
        ha[tid] = tanhf(a);
    }
    __syncthreads();

    {   // T2 = ql @ Pxy
        int c = tid >> 2, j0 = (tid & 3)*16;
        float acc[16];
#pragma unroll
        for (int v = 0; v < 16; ++v) acc[v] = 0.f;
        for (int i = 0; i < 64; ++i) {
            float a = ql[c*64+i];
            const float* pr = Pxy + i*64 + j0;
#pragma unroll
            for (int v = 0; v < 16; ++v) acc[v] += a*pr[v];
        }
#pragma unroll
        for (int v = 0; v < 16; ++v) T2[c*64+j0+v] = acc[v];
    }
    __syncthreads();
    {   // S = T2 @ kl^T
        int c = tid >> 2, d0 = (tid & 3)*16;
        float acc[16];
#pragma unroll
        for (int v = 0; v < 16; ++v) acc[v] = 0.f;
        for (int j = 0; j < 64; ++j) {
            float a = T2[c*64+j];
#pragma unroll
            for (int v = 0; v < 16; ++v) acc[v] += a*kl[(d0+v)*64+j];
        }
#pragma unroll
        for (int v = 0; v < 16; ++v) S[c*64+d0+v] = acc[v];
    }
    __syncthreads();
    {   // T2 = ql @ Pxx -> nq2
        int c = tid >> 2, j0 = (tid & 3)*16;
        float acc[16];
#pragma unroll
        for (int v = 0; v < 16; ++v) acc[v] = 0.f;
        for (int i = 0; i < 64; ++i) {
            float a = ql[c*64+i];
            const float* pr = Pxx + i*64 + j0;
#pragma unroll
            for (int v = 0; v < 16; ++v) acc[v] += a*pr[v];
        }
#pragma unroll
        for (int v = 0; v < 16; ++v) T2[c*64+j0+v] = acc[v];
    }
    __syncthreads();
    if (tid < 64) {
        float a = 0.f;
        for (int j = 0; j < 64; ++j) a += T2[tid*64+j]*ql[tid*64+j];
        nq2[tid] = a;
    }
    __syncthreads();
    {   // T2 = kl @ Pyy -> nk2
        int c = tid >> 2, j0 = (tid & 3)*16;
        float acc[16];
#pragma unroll
        for (int v = 0; v < 16; ++v) acc[v] = 0.f;
        for (int i = 0; i < 64; ++i) {
            float a = kl[c*64+i];
            const float* pr = Pyy + i*64 + j0;
#pragma unroll
            for (int v = 0; v < 16; ++v) acc[v] += a*pr[v];
        }
#pragma unroll
        for (int v = 0; v < 16; ++v) T2[c*64+j0+v] = acc[v];
    }
    __syncthreads();
    if (tid < 64) {
        float a = 0.f;
        for (int j = 0; j < 64; ++j) a += T2[tid*64+j]*kl[tid*64+j];
        nk2[tid] = a;
    }
    __syncthreads();

    if (tid < 64) {
        int c = tid, h = c >> 3;
        float dq = fmaxf(sqrtf(nq2[c]), 1e-12f);
        float tt = temp[h];
        float v[8]; float mx = -1e30f;
#pragma unroll
        for (int dd = 0; dd < 8; ++dd) {
            int d = h*8 + dd;
            float dk = fmaxf(sqrtf(nk2[d]), 1e-12f);
            v[dd] = S[c*64+d] / (dq*dk) * tt;
            mx = fmaxf(mx, v[dd]);
        }
        float sum = 0.f;
#pragma unroll
        for (int dd = 0; dd < 8; ++dd) { v[dd] = expf(v[dd]-mx); sum += v[dd]; }
        float inv = 1.f/sum;
#pragma unroll
        for (int dd = 0; dd < 8; ++dd) A[c*8+dd] = v[dd]*inv;
    }
    __syncthreads();

    {   // S := blockdiag(A) @ vl ; T2 := diag(ha) @ vh
        int c = tid >> 2, i0 = (tid & 3)*16, h = c >> 3;
        float acc[16];
#pragma unroll
        for (int v = 0; v < 16; ++v) acc[v] = 0.f;
#pragma unroll
        for (int dd = 0; dd < 8; ++dd) {
            float a = A[c*8+dd];
            const float* vr = vl + (h*8+dd)*64 + i0;
#pragma unroll
            for (int v = 0; v < 16; ++v) acc[v] += a*vr[v];
        }
#pragma unroll
        for (int v = 0; v < 16; ++v) S[c*64+i0+v] = acc[v];
        float hac = ha[c];
#pragma unroll
        for (int v = 0; v < 16; ++v) T2[c*64+i0+v] = hac*vh[c*64+i0+v];
    }
    __syncthreads();

    {   // M1 = proj @ T2 ; M2 = proj @ S
        int o = tid >> 2, i0 = (tid & 3)*16;
        float a1[16], a2[16];
#pragma unroll
        for (int v = 0; v < 16; ++v) { a1[v] = 0.f; a2[v] = 0.f; }
        for (int c = 0; c < 64; ++c) {
            float p = proj[o*64+c];
            const float* u  = T2 + c*64 + i0;
            const float* bm = S  + c*64 + i0;
#pragma unroll
            for (int v = 0; v < 16; ++v) { a1[v] += p*u[v]; a2[v] += p*bm[v]; }
        }
#pragma unroll
        for (int v = 0; v < 16; ++v) {
            g_M1[b*4096 + o*64 + i0 + v] = a1[v];
            g_M2[b*4096 + o*64 + i0 + v] = a2[v];
        }
    }
}

// ---------------- K5: out = M1 @ x_h + M2 @ y, 4x4 conflict-free (R4 measured) ---------
__global__ __launch_bounds__(256, 2)
void k5_final(const float* __restrict__ y, float* __restrict__ out) {
    extern __shared__ float sm[];
    float* m1 = sm;                 // [64][65]
    float* m2 = sm + 64*65;
    float* sa = sm + 2*64*65;       // x_h chunk [64][132]
    float* sb = sa + 64*132;        // y   chunk [64][132]

    const int b = blockIdx.y;
    const int tid = threadIdx.x;
    const int n0 = blockIdx.x * 128;

    for (int li = tid; li < 4096; li += 256) {
        int o = li >> 6, k = li & 63;
        m1[o*65+k] = g_M1[b*4096 + li];
        m2[o*65+k] = g_M2[b*4096 + li];
    }
    for (int li = tid; li < 2048; li += 256) {
        int cc = li >> 5, t4 = (li & 31) * 4;
        size_t go = ((size_t)(b*C64 + cc) << 16) + n0 + t4;
        *(float4*)&sa[cc*132 + t4] = *(const float4*)&g_xh[go];
        *(float4*)&sb[cc*132 + t4] = *(const float4*)&y[go];
    }
    __syncthreads();

    const int o0 = (tid >> 4) * 4;
    const int l  = tid & 15;
    ull acc[4][4];
#pragma unroll
    for (int u = 0; u < 4; ++u)
#pragma unroll
        for (int v = 0; v < 4; ++v) acc[u][v] = 0ULL;

#pragma unroll 4
    for (int k = 0; k < 64; ++k) {
        ull a1p[4], a2p[4];
#pragma unroll
        for (int u = 0; u < 4; ++u) {
            float a1 = m1[(o0+u)*65 + k];
            float a2 = m2[(o0+u)*65 + k];
            a1p[u] = pk2(a1, a1);
            a2p[u] = pk2(a2, a2);
        }
        ull bx[4], by[4];
#pragma unroll
        for (int v = 0; v < 4; ++v) {
            bx[v] = *(const ull*)&sa[k*132 + 2*l + 32*v];
            by[v] = *(const ull*)&sb[k*132 + 2*l + 32*v];
        }
#pragma unroll
        for (int u = 0; u < 4; ++u)
#pragma unroll
            for (int v = 0; v < 4; ++v) {
                fma2(acc[u][v], a1p[u], bx[v]);
                fma2(acc[u][v], a2p[u], by[v]);
            }
    }
#pragma unroll
    for (int u = 0; u < 4; ++u) {
        float* op = out + (size_t)(b*C64 + o0 + u)*HW_ + n0 + 2*l;
#pragma unroll
        for (int v = 0; v < 4; ++v) {
            float2 f = unpk2(acc[u][v]);
            *(float2*)(op + 32*v) = f;
        }
    }
}

// ---------------- launcher ----------------
extern "C" void kernel_launch(void* const* d_in, const int* in_sizes, int n_in,
                              void* d_out, int out_size) {
    (void)in_sizes; (void)n_in; (void)out_size;
    const float* x      = (const float*)d_in[0];
    const float* y      = (const float*)d_in[1];
    const float* h1w3   = (const float*)d_in[2];
    const float* h1w5   = (const float*)d_in[3];
    const float* h1w7   = (const float*)d_in[4];
    const float* h2w3   = (const float*)d_in[5];
    const float* h2w5   = (const float*)d_in[6];
    const float* h2w7   = (const float*)d_in[7];
    const float* qh_w   = (const float*)d_in[8];
    const float* kh_w   = (const float*)d_in[9];
    const float* vh_w   = (const float*)d_in[10];
    const float* ql_w   = (const float*)d_in[11];
    const float* kl_w   = (const float*)d_in[12];
    const float* vl_w   = (const float*)d_in[13];
    const float* proj_w = (const float*)d_in[14];
    const float* w1     = (const float*)d_in[15];
    const float* w2     = (const float*)d_in[16];
    const float* temp   = (const float*)d_in[17];
    float* out = (float*)d_out;

    const int SMEM_GEMM = 2*64*130*4;               // 66560
    const int SMEM5     = (2*64*65 + 2*64*132)*4;   // 100864
    cudaFuncSetAttribute(k3_cxy,     cudaFuncAttributeMaxDynamicSharedMemorySize, SMEM_GEMM);
    cudaFuncSetAttribute(k2_moments, cudaFuncAttributeMaxDynamicSharedMemorySize, SMEM_GEMM);
    cudaFuncSetAttribute(k5_final,   cudaFuncAttributeMaxDynamicSharedMemorySize, SMEM5);

    // order: kz_a(0), k1(1), kz_b(2), k2(3) <- ncu profiles launch index 3
    kz_a<<<64, 256>>>();
    k1_dwconv_pool<<<dim3(16, 64, 8), 256>>>(x, y, h1w3, h1w5, h1w7, h2w3, h2w5, h2w7);
    kz_b<<<64, 256>>>();
    k2_moments<<<dim3(37, B_), 256, SMEM_GEMM>>>();
    k3_cxy<<<dim3(74, B_), 256, SMEM_GEMM>>>();
    k4_finalize<<<B_, 256>>>(qh_w, kh_w, vh_w, ql_w, kl_w, vl_w, proj_w, w1, w2, temp);
    k5_final<<<dim3(HW_/128, B_), 256, SMEM5>>>(y, out);
}

// round 12
// speedup vs baseline: 1.0959x; 1.0013x over previous
#include <cuda_runtime.h>
#include <cuda_bf16.h>
#include <math.h>

#define B_   4
#define C64  64
#define H_   256
#define W_   256
#define HW_  65536
#define PW_  128
#define PHW_ 16384

typedef unsigned long long ull;

// ---------------- f32x2 packed helpers ----------------
__device__ __forceinline__ ull pk2(float lo, float hi) {
    ull r;
    asm("mov.b64 %0, {%1, %2};" : "=l"(r) : "f"(lo), "f"(hi));
    return r;
}
__device__ __forceinline__ void fma2(ull& d, ull a, ull b) {
    asm("fma.rn.f32x2 %0, %1, %2, %0;" : "+l"(d) : "l"(a), "l"(b));
}
__device__ __forceinline__ float2 unpk2(ull v) {
    float lo, hi;
    asm("mov.b64 {%0, %1}, %2;" : "=f"(lo), "=f"(hi) : "l"(v));
    return make_float2(lo, hi);
}

// ---------------- scratch (zero-initialized at module load; k4 re-zeros after use) -----
__device__ float g_xh[B_*C64*HW_];
__device__ float g_yh[B_*C64*HW_];
__device__ float g_px[B_*C64*PHW_];
__device__ float g_py[B_*C64*PHW_];
__device__ float g_Cxy[B_*4096];
__device__ float g_Pxx[B_*4096];
__device__ float g_Pyy[B_*4096];
__device__ float g_Pxy[B_*4096];
__device__ float g_M1[B_*4096];
__device__ float g_M2[B_*4096];

// ---------------- K1: depthwise conv + avgpool, 64x64 tile, 4x4 per thread (R6/R9) -----
template<int K>
__device__ __forceinline__ void conv4(const float (*s)[72], const float2* __restrict__ wps,
                                      int rq, int cq, float4 out[4]) {
    const int hoff = 4 - K/2;
    const int base_r = 4*rq + 3 - K/2;
    const int xb = 4*cq;

    ull accA[4], accB[4];
#pragma unroll
    for (int c = 0; c < 4; ++c) { accA[c] = 0ULL; accB[c] = 0ULL; }

    float P[12], Cr[12];
    {
        float4 a = *(const float4*)&s[base_r][xb];
        float4 b = *(const float4*)&s[base_r][xb+4];
        float4 c = *(const float4*)&s[base_r][xb+8];
        P[0]=a.x;P[1]=a.y;P[2]=a.z;P[3]=a.w;P[4]=b.x;P[5]=b.y;P[6]=b.z;P[7]=b.w;
        P[8]=c.x;P[9]=c.y;P[10]=c.z;P[11]=c.w;
    }
#pragma unroll
    for (int m = 1; m <= K+2; ++m) {
        {
            float4 a = *(const float4*)&s[base_r+m][xb];
            float4 b = *(const float4*)&s[base_r+m][xb+4];
            float4 c = *(const float4*)&s[base_r+m][xb+8];
            Cr[0]=a.x;Cr[1]=a.y;Cr[2]=a.z;Cr[3]=a.w;Cr[4]=b.x;Cr[5]=b.y;Cr[6]=b.z;Cr[7]=b.w;
            Cr[8]=c.x;Cr[9]=c.y;Cr[10]=c.z;Cr[11]=c.w;
        }
        ull pv[K+3];
#pragma unroll
        for (int i = 0; i < K+3; ++i) pv[i] = pk2(P[hoff+i], Cr[hoff+i]);
        const int mp = m - 1;
        if (mp <= K-1) {
#pragma unroll
            for (int dx = 0; dx < K; ++dx) {
                ull wp = *(const ull*)&wps[mp*K + dx];
#pragma unroll
                for (int c = 0; c < 4; ++c) fma2(accA[c], wp, pv[dx+c]);
            }
        }
        if (mp >= 2) {
#pragma unroll
            for (int dx = 0; dx < K; ++dx) {
                ull wp = *(const ull*)&wps[(mp-2)*K + dx];
#pragma unroll
                for (int c = 0; c < 4; ++c) fma2(accB[c], wp, pv[dx+c]);
            }
        }
#pragma unroll
        for (int i = 0; i < 12; ++i) P[i] = Cr[i];
    }
    float2 a0 = unpk2(accA[0]), a1 = unpk2(accA[1]), a2 = unpk2(accA[2]), a3 = unpk2(accA[3]);
    float2 b0 = unpk2(accB[0]), b1 = unpk2(accB[1]), b2 = unpk2(accB[2]), b3 = unpk2(accB[3]);
    out[0] = make_float4(a0.x, a1.x, a2.x, a3.x);
    out[1] = make_float4(a0.y, a1.y, a2.y, a3.y);
    out[2] = make_float4(b0.x, b1.x, b2.x, b3.x);
    out[3] = make_float4(b0.y, b1.y, b2.y, b3.y);
}

__global__ __launch_bounds__(256)
void k1_dwconv_pool(const float* __restrict__ x, const float* __restrict__ y,
                    const float* __restrict__ h1w3, const float* __restrict__ h1w5,
                    const float* __restrict__ h1w7,
                    const float* __restrict__ h2w3, const float* __restrict__ h2w5,
                    const float* __restrict__ h2w7) {
    __shared__ float s[70][72];
    __shared__ float2 wps[49];

    const int c = blockIdx.y;
    const int z = blockIdx.z;
    const int b = z >> 1;
    const int which = z & 1;
    const int ty0 = (blockIdx.x >> 2) * 64;
    const int tx0 = (blockIdx.x & 3) * 64;
    const int tid = threadIdx.x;

    const float* src = which ? y : x;
    const float* w3  = which ? h2w3 : h1w3;
    const float* w5  = which ? h2w5 : h1w5;
    const float* w7  = which ? h2w7 : h1w7;
    float* dst  = which ? g_yh : g_xh;
    float* pdst = which ? g_py : g_px;

    const float* wp; int wn;
    if (c < 32)      { wp = w3 + c*9;        wn = 9;  }
    else if (c < 48) { wp = w5 + (c-32)*25;  wn = 25; }
    else             { wp = w7 + (c-48)*49;  wn = 49; }
    if (tid < wn) { float w = wp[tid]; wps[tid] = make_float2(w, w); }

    const float* base = src + (size_t)(b*C64 + c) * HW_;
    for (int i = tid; i < 70*18; i += 256) {
        int r = i / 18, q = i - r*18;
        int gy = ty0 - 3 + r, gx = tx0 - 4 + q*4;
        float4 v = make_float4(0.f, 0.f, 0.f, 0.f);
        if ((unsigned)gy < 256u && (unsigned)gx <= 252u)
            v = *(const float4*)&base[gy*W_ + gx];
        *(float4*)&s[r][q*4] = v;
    }
    __syncthreads();

    const int rq = tid >> 4;
    const int cq = tid & 15;
    float4 o[4];
    if (c < 32)      conv4<3>(s, wps, rq, cq, o);
    else if (c < 48) conv4<5>(s, wps, rq, cq, o);
    else             conv4<7>(s, wps, rq, cq, o);

    float* dplane = dst + (size_t)(b*C64 + c) * HW_;
#pragma unroll
    for (int t = 0; t < 4; ++t)
        *(float4*)&dplane[(ty0 + 4*rq + t)*W_ + tx0 + 4*cq] = o[t];

    {
        const int pr  = tid >> 3;
        const int pc4 = (tid & 7) * 4;
        float4 pv;
        float* e = &pv.x;
#pragma unroll
        for (int d = 0; d < 4; ++d) {
            int pc = pc4 + d;
            e[d] = 0.25f * (s[2*pr+3][2*pc+4] + s[2*pr+3][2*pc+5] +
                            s[2*pr+4][2*pc+4] + s[2*pr+4][2*pc+5]);
        }
        float* pplane = pdst + (size_t)(b*C64 + c) * PHW_;
        *(float4*)&pplane[(ty0/2 + pr)*PW_ + tx0/2 + pc4] = pv;
    }
}

// ---------------- K2 merged: Pxx, Pyy, Pxy in one pass (R9 measured, 61 us) ------------
__global__ __launch_bounds__(256, 1)
void k2_moments() {
    extern __shared__ float sm[];
    float* sx = sm;               // [64][130]
    float* sy = sm + 64*130;
    const int b = blockIdx.y;
    const int tid = threadIdx.x;
    const int q = tid >> 4;
    const int l = tid & 15;
    ull axx[16], ayy[16], axy[16];
#pragma unroll
    for (int u = 0; u < 16; ++u) { axx[u] = 0ULL; ayy[u] = 0ULL; axy[u] = 0ULL; }

    for (int chunk = blockIdx.x; chunk < PHW_/128; chunk += gridDim.x) {
        const int n0 = chunk * 128;
        __syncthreads();
        for (int li = tid; li < 2048; li += 256) {
            int cc = li >> 5, t4 = (li & 31) * 4;
            size_t go = ((size_t)(b*C64 + cc) << 14) + n0 + t4;
            float4 vx = *(const float4*)&g_px[go];
            float4 vy = *(const float4*)&g_py[go];
            *(float2*)&sx[cc*130 + t4]     = make_float2(vx.x, vx.y);
            *(float2*)&sx[cc*130 + t4 + 2] = make_float2(vx.z, vx.w);
            *(float2*)&sy[cc*130 + t4]     = make_float2(vy.x, vy.y);
            *(float2*)&sy[cc*130 + t4 + 2] = make_float2(vy.z, vy.w);
        }
        __syncthreads();
#pragma unroll 2
        for (int t = 0; t < 128; t += 2) {
            ull ax[4], bx[4], ay[4], by[4];
#pragma unroll
            for (int u = 0; u < 4; ++u) {
                ax[u] = *(const ull*)&sx[(q + 16*u)*130 + t];
                bx[u] = *(const ull*)&sx[(l + 16*u)*130 + t];
                ay[u] = *(const ull*)&sy[(q + 16*u)*130 + t];
                by[u] = *(const ull*)&sy[(l + 16*u)*130 + t];
            }
#pragma unroll
            for (int u = 0; u < 4; ++u)
#pragma unroll
                for (int v = 0; v < 4; ++v) {
                    fma2(axx[u*4+v], ax[u], bx[v]);
                    fma2(ayy[u*4+v], ay[u], by[v]);
                    fma2(axy[u*4+v], ax[u], by[v]);
                }
        }
    }
#pragma unroll
    for (int u = 0; u < 4; ++u)
#pragma unroll
        for (int v = 0; v < 4; ++v) {
            float2 fx = unpk2(axx[u*4+v]);
            float2 fy = unpk2(ayy[u*4+v]);
            float2 fz = unpk2(axy[u*4+v]);
            int o = b*4096 + (q+16*u)*64 + (l+16*v);
            atomicAdd(&g_Pxx[o], fx.x + fx.y);
            atomicAdd(&g_Pyy[o], fy.x + fy.y);
            atomicAdd(&g_Pxy[o], fz.x + fz.y);
        }
}

// ---------------- K3: Cxy = x_h @ y_h^T, 4x4 tiles, register double-buffered (R5) ------
__global__ __launch_bounds__(256, 2)
void k3_cxy() {
    extern __shared__ float sm[];
    float* sx = sm;               // [64][130]
    float* sy = sm + 64*130;
    const int b = blockIdx.y;
    const int tid = threadIdx.x;
    const int q = tid >> 4;
    const int l = tid & 15;
    const int cc0 = tid >> 5;          // 0..7 (row base for fills)
    const int t4  = (tid & 31) * 4;    // 0..124
    ull acc[16];
#pragma unroll
    for (int u = 0; u < 16; ++u) acc[u] = 0ULL;

    const int NCH = HW_/128;
    float4 rx[4], ry[4];
    int chunk = blockIdx.x;
    {
        int n0 = chunk * 128;
#pragma unroll
        for (int k = 0; k < 4; ++k) {
            size_t go = ((size_t)(b*C64 + cc0 + 8*k) << 16) + n0 + t4;
            rx[k] = *(const float4*)&g_xh[go];
            ry[k] = *(const float4*)&g_yh[go];
        }
    }
    while (true) {
        __syncthreads();
#pragma unroll
        for (int k = 0; k < 4; ++k) {
            int cc = cc0 + 8*k;
            *(float2*)&sx[cc*130 + t4]     = make_float2(rx[k].x, rx[k].y);
            *(float2*)&sx[cc*130 + t4 + 2] = make_float2(rx[k].z, rx[k].w);
            *(float2*)&sy[cc*130 + t4]     = make_float2(ry[k].x, ry[k].y);
            *(float2*)&sy[cc*130 + t4 + 2] = make_float2(ry[k].z, ry[k].w);
        }
        __syncthreads();
        const int next = chunk + gridDim.x;
        if (next < NCH) {
            int n0 = next * 128;
#pragma unroll
            for (int k = 0; k < 4; ++k) {
                size_t go = ((size_t)(b*C64 + cc0 + 8*k) << 16) + n0 + t4;
                rx[k] = *(const float4*)&g_xh[go];
                ry[k] = *(const float4*)&g_yh[go];
            }
        }
#pragma unroll 4
        for (int t = 0; t < 128; t += 2) {
            ull ax[4], by[4];
#pragma unroll
            for (int u = 0; u < 4; ++u) {
                ax[u] = *(const ull*)&sx[(q + 16*u)*130 + t];
                by[u] = *(const ull*)&sy[(l + 16*u)*130 + t];
            }
#pragma unroll
            for (int u = 0; u < 4; ++u)
#pragma unroll
                for (int v = 0; v < 4; ++v)
                    fma2(acc[u*4+v], ax[u], by[v]);
        }
        if (next >= NCH) break;
        chunk = next;
    }
#pragma unroll
    for (int u = 0; u < 4; ++u)
#pragma unroll
        for (int v = 0; v < 4; ++v) {
            float2 f = unpk2(acc[u*4+v]);
            atomicAdd(&g_Cxy[b*4096 + (q+16*u)*64 + (l+16*v)], f.x + f.y);
        }
}

// ---------------- K4: per-batch finalize -> M1, M2 (+ re-zero accumulators) ------------
__global__ void k4_finalize(const float* __restrict__ qh, const float* __restrict__ kh,
                            const float* __restrict__ vh, const float* __restrict__ ql,
                            const float* __restrict__ kl, const float* __restrict__ vl,
                            const float* __restrict__ proj,
                            const float* __restrict__ w1, const float* __restrict__ w2,
                            const float* __restrict__ temp) {
    __shared__ float T2[4096];
    __shared__ float S[4096];
    __shared__ float pooled[64], hidden[16], ha[64], nq2[64], nk2[64];
    __shared__ float A[512];
    __shared__ float psum[256];

    const int b = blockIdx.x, tid = threadIdx.x;
    const float* Cxy = g_Cxy + b*4096;
    const float* Pxx = g_Pxx + b*4096;
    const float* Pyy = g_Pyy + b*4096;
    const float* Pxy = g_Pxy + b*4096;

    {
        int c = tid & 63, qq = tid >> 6;
        float acc = 0.f;
        for (int i = qq*16; i < qq*16 + 16; ++i) {
            const float* cr = Cxy + i*64;
            const float* kr = kh + c*64;
            float s0=0,s1=0,s2=0,s3=0;
            for (int j = 0; j < 64; j += 4) {
                s0 += cr[j  ]*kr[j  ]; s1 += cr[j+1]*kr[j+1];
                s2 += cr[j+2]*kr[j+2]; s3 += cr[j+3]*kr[j+3];
            }
            acc += qh[c*64+i]*(s0+s1+s2+s3);
        }
        psum[tid] = acc;
        __syncthreads();
        if (tid < 64) pooled[tid] = (psum[tid]+psum[tid+64]+psum[tid+128]+psum[tid+192]) * (1.0f/(float)HW_);
        __syncthreads();
    }
    if (tid < 16) {
        float a = 0.f;
        for (int cc = 0; cc < 64; ++cc) a += w1[tid*64+cc]*pooled[cc];
        hidden[tid] = fmaxf(a, 0.f);
    }
    __syncthreads();
    if (tid < 64) {
        float a = 0.f;
        for (int j = 0; j < 16; ++j) a += w2[tid*16+j]*hidden[j];
        ha[tid] = tanhf(a);
    }
    __syncthreads();

    {   // T2 = ql @ Pxy
        int c = tid >> 2, j0 = (tid & 3)*16;
        float acc[16];
#pragma unroll
        for (int v = 0; v < 16; ++v) acc[v] = 0.f;
        for (int i = 0; i < 64; ++i) {
            float a = ql[c*64+i];
            const float* pr = Pxy + i*64 + j0;
#pragma unroll
            for (int v = 0; v < 16; ++v) acc[v] += a*pr[v];
        }
#pragma unroll
        for (int v = 0; v < 16; ++v) T2[c*64+j0+v] = acc[v];
    }
    __syncthreads();
    {   // S = T2 @ kl^T
        int c = tid >> 2, d0 = (tid & 3)*16;
        float acc[16];
#pragma unroll
        for (int v = 0; v < 16; ++v) acc[v] = 0.f;
        for (int j = 0; j < 64; ++j) {
            float a = T2[c*64+j];
#pragma unroll
            for (int v = 0; v < 16; ++v) acc[v] += a*kl[(d0+v)*64+j];
        }
#pragma unroll
        for (int v = 0; v < 16; ++v) S[c*64+d0+v] = acc[v];
    }
    __syncthreads();
    {   // T2 = ql @ Pxx -> nq2
        int c = tid >> 2, j0 = (tid & 3)*16;
        float acc[16];
#pragma unroll
        for (int v = 0; v < 16; ++v) acc[v] = 0.f;
        for (int i = 0; i < 64; ++i) {
            float a = ql[c*64+i];
            const float* pr = Pxx + i*64 + j0;
#pragma unroll
            for (int v = 0; v < 16; ++v) acc[v] += a*pr[v];
        }
#pragma unroll
        for (int v = 0; v < 16; ++v) T2[c*64+j0+v] = acc[v];
    }
    __syncthreads();
    if (tid < 64) {
        float a = 0.f;
        for (int j = 0; j < 64; ++j) a += T2[tid*64+j]*ql[tid*64+j];
        nq2[tid] = a;
    }
    __syncthreads();
    {   // T2 = kl @ Pyy -> nk2
        int c = tid >> 2, j0 = (tid & 3)*16;
        float acc[16];
#pragma unroll
        for (int v = 0; v < 16; ++v) acc[v] = 0.f;
        for (int i = 0; i < 64; ++i) {
            float a = kl[c*64+i];
            const float* pr = Pyy + i*64 + j0;
#pragma unroll
            for (int v = 0; v < 16; ++v) acc[v] += a*pr[v];
        }
#pragma unroll
        for (int v = 0; v < 16; ++v) T2[c*64+j0+v] = acc[v];
    }
    __syncthreads();
    if (tid < 64) {
        float a = 0.f;
        for (int j = 0; j < 64; ++j) a += T2[tid*64+j]*kl[tid*64+j];
        nk2[tid] = a;
    }
    __syncthreads();

    if (tid < 64) {
        int c = tid, h = c >> 3;
        float dq = fmaxf(sqrtf(nq2[c]), 1e-12f);
        float tt = temp[h];
        float v[8]; float mx = -1e30f;
#pragma unroll
        for (int dd = 0; dd < 8; ++dd) {
            int d = h*8 + dd;
            float dk = fmaxf(sqrtf(nk2[d]), 1e-12f);
            v[dd] = S[c*64+d] / (dq*dk) * tt;
            mx = fmaxf(mx, v[dd]);
        }
        float sum = 0.f;
#pragma unroll
        for (int dd = 0; dd < 8; ++dd) { v[dd] = expf(v[dd]-mx); sum += v[dd]; }
        float inv = 1.f/sum;
#pragma unroll
        for (int dd = 0; dd < 8; ++dd) A[c*8+dd] = v[dd]*inv;
    }
    __syncthreads();

    {   // S := blockdiag(A) @ vl ; T2 := diag(ha) @ vh
        int c = tid >> 2, i0 = (tid & 3)*16, h = c >> 3;
        float acc[16];
#pragma unroll
        for (int v = 0; v < 16; ++v) acc[v] = 0.f;
#pragma unroll
        for (int dd = 0; dd < 8; ++dd) {
            float a = A[c*8+dd];
            const float* vr = vl + (h*8+dd)*64 + i0;
#pragma unroll
            for (int v = 0; v < 16; ++v) acc[v] += a*vr[v];
        }
#pragma unroll
        for (int v = 0; v < 16; ++v) S[c*64+i0+v] = acc[v];
        float hac = ha[c];
#pragma unroll
        for (int v = 0; v < 16; ++v) T2[c*64+i0+v] = hac*vh[c*64+i0+v];
    }
    __syncthreads();

    {   // M1 = proj @ T2 ; M2 = proj @ S
        int o = tid >> 2, i0 = (tid & 3)*16;
        float a1[16], a2[16];
#pragma unroll
        for (int v = 0; v < 16; ++v) { a1[v] = 0.f; a2[v] = 0.f; }
        for (int c = 0; c < 64; ++c) {
            float p = proj[o*64+c];
            const float* u  = T2 + c*64 + i0;
            const float* bm = S  + c*64 + i0;
#pragma unroll
            for (int v = 0; v < 16; ++v) { a1[v] += p*u[v]; a2[v] += p*bm[v]; }
        }
#pragma unroll
        for (int v = 0; v < 16; ++v) {
            g_M1[b*4096 + o*64 + i0 + v] = a1[v];
            g_M2[b*4096 + o*64 + i0 + v] = a2[v];
        }
    }

    // re-zero this batch's accumulators for the next graph replay (all reads done above;
    // __device__ globals start zeroed at load, so the invariant holds for every run)
    {
        float4 z = make_float4(0.f, 0.f, 0.f, 0.f);
#pragma unroll
        for (int t = 0; t < 4; ++t) {
            int off = b*4096 + tid*16 + t*4;
            *(float4*)&g_Cxy[off] = z;
            *(float4*)&g_Pxx[off] = z;
            *(float4*)&g_Pyy[off] = z;
            *(float4*)&g_Pxy[off] = z;
        }
    }
}

// ---------------- K5: out = M1 @ x_h + M2 @ y, 4x4 conflict-free (R4/R9 measured) ------
__global__ __launch_bounds__(256, 2)
void k5_final(const float* __restrict__ y, float* __restrict__ out) {
    extern __shared__ float sm[];
    float* m1 = sm;                 // [64][65]
    float* m2 = sm + 64*65;
    float* sa = sm + 2*64*65;       // x_h chunk [64][132]
    float* sb = sa + 64*132;        // y   chunk [64][132]

    const int b = blockIdx.y;
    const int tid = threadIdx.x;
    const int n0 = blockIdx.x * 128;

    for (int li = tid; li < 4096; li += 256) {
        int o = li >> 6, k = li & 63;
        m1[o*65+k] = g_M1[b*4096 + li];
        m2[o*65+k] = g_M2[b*4096 + li];
    }
    for (int li = tid; li < 2048; li += 256) {
        int cc = li >> 5, t4 = (li & 31) * 4;
        size_t go = ((size_t)(b*C64 + cc) << 16) + n0 + t4;
        *(float4*)&sa[cc*132 + t4] = *(const float4*)&g_xh[go];
        *(float4*)&sb[cc*132 + t4] = *(const float4*)&y[go];
    }
    __syncthreads();

    const int o0 = (tid >> 4) * 4;
    const int l  = tid & 15;
    ull acc[4][4];
#pragma unroll
    for (int u = 0; u < 4; ++u)
#pragma unroll
        for (int v = 0; v < 4; ++v) acc[u][v] = 0ULL;

#pragma unroll 4
    for (int k = 0; k < 64; ++k) {
        ull a1p[4], a2p[4];
#pragma unroll
        for (int u = 0; u < 4; ++u) {
            float a1 = m1[(o0+u)*65 + k];
            float a2 = m2[(o0+u)*65 + k];
            a1p[u] = pk2(a1, a1);
            a2p[u] = pk2(a2, a2);
        }
        ull bx[4], by[4];
#pragma unroll
        for (int v = 0; v < 4; ++v) {
            bx[v] = *(const ull*)&sa[k*132 + 2*l + 32*v];
            by[v] = *(const ull*)&sb[k*132 + 2*l + 32*v];
        }
#pragma unroll
        for (int u = 0; u < 4; ++u)
#pragma unroll
            for (int v = 0; v < 4; ++v) {
                fma2(acc[u][v], a1p[u], bx[v]);
                fma2(acc[u][v], a2p[u], by[v]);
            }
    }
#pragma unroll
    for (int u = 0; u < 4; ++u) {
        float* op = out + (size_t)(b*C64 + o0 + u)*HW_ + n0 + 2*l;
#pragma unroll
        for (int v = 0; v < 4; ++v) {
            float2 f = unpk2(acc[u][v]);
            *(float2*)(op + 32*v) = f;
        }
    }
}

// ---------------- launcher ----------------
extern "C" void kernel_launch(void* const* d_in, const int* in_sizes, int n_in,
                              void* d_out, int out_size) {
    (void)in_sizes; (void)n_in; (void)out_size;
    const float* x      = (const float*)d_in[0];
    const float* y      = (const float*)d_in[1];
    const float* h1w3   = (const float*)d_in[2];
    const float* h1w5   = (const float*)d_in[3];
    const float* h1w7   = (const float*)d_in[4];
    const float* h2w3   = (const float*)d_in[5];
    const float* h2w5   = (const float*)d_in[6];
    const float* h2w7   = (const float*)d_in[7];
    const float* qh_w   = (const float*)d_in[8];
    const float* kh_w   = (const float*)d_in[9];
    const float* vh_w   = (const float*)d_in[10];
    const float* ql_w   = (const float*)d_in[11];
    const float* kl_w   = (const float*)d_in[12];
    const float* vl_w   = (const float*)d_in[13];
    const float* proj_w = (const float*)d_in[14];
    const float* w1     = (const float*)d_in[15];
    const float* w2     = (const float*)d_in[16];
    const float* temp   = (const float*)d_in[17];
    float* out = (float*)d_out;

    const int SMEM_GEMM = 2*64*130*4;               // 66560
    const int SMEM5     = (2*64*65 + 2*64*132)*4;   // 100864
    cudaFuncSetAttribute(k3_cxy,     cudaFuncAttributeMaxDynamicSharedMemorySize, SMEM_GEMM);
    cudaFuncSetAttribute(k2_moments, cudaFuncAttributeMaxDynamicSharedMemorySize, SMEM_GEMM);
    cudaFuncSetAttribute(k5_final,   cudaFuncAttributeMaxDynamicSharedMemorySize, SMEM5);

    // order: k1(0), k2(1), k3(2), k4(3) <- ncu profiles launch index 3, k5(4)
    k1_dwconv_pool<<<dim3(16, 64, 8), 256>>>(x, y, h1w3, h1w5, h1w7, h2w3, h2w5, h2w7);
    k2_moments<<<dim3(37, B_), 256, SMEM_GEMM>>>();
    k3_cxy<<<dim3(74, B_), 256, SMEM_GEMM>>>();
    k4_finalize<<<B_, 256>>>(qh_w, kh_w, vh_w, ql_w, kl_w, vl_w, proj_w, w1, w2, temp);
    k5_final<<<dim3(HW_/128, B_), 256, SMEM5>>>(y, out);
}

// round 15
// speedup vs baseline: 1.5087x; 1.3767x over previous
#include <cuda_runtime.h>
#include <cuda_bf16.h>
#include <math.h>

#define B_   4
#define C64  64
#define H_   256
#define W_   256
#define HW_  65536
#define PW_  128
#define PHW_ 16384
#define ST   68   // padded row stride for k4 smem matrices; mult of 4 -> float4-aligned rows

typedef unsigned long long ull;

// ---------------- f32x2 packed helpers ----------------
__device__ __forceinline__ ull pk2(float lo, float hi) {
    ull r;
    asm("mov.b64 %0, {%1, %2};" : "=l"(r) : "f"(lo), "f"(hi));
    return r;
}
__device__ __forceinline__ void fma2(ull& d, ull a, ull b) {
    asm("fma.rn.f32x2 %0, %1, %2, %0;" : "+l"(d) : "l"(a), "l"(b));
}
__device__ __forceinline__ float2 unpk2(ull v) {
    float lo, hi;
    asm("mov.b64 {%0, %1}, %2;" : "=f"(lo), "=f"(hi) : "l"(v));
    return make_float2(lo, hi);
}

// ---------------- scratch (zero-initialized at module load; k4 re-zeros after use) -----
__device__ float g_xh[B_*C64*HW_];
__device__ float g_yh[B_*C64*HW_];
__device__ float g_px[B_*C64*PHW_];
__device__ float g_py[B_*C64*PHW_];
__device__ float g_Cxy[B_*4096];
__device__ float g_Pxx[B_*4096];
__device__ float g_Pyy[B_*4096];
__device__ float g_Pxy[B_*4096];
__device__ float g_M1[B_*4096];
__device__ float g_M2[B_*4096];

// ---------------- K1: depthwise conv + avgpool, 64x64 tile, 4x4 per thread (R6/R9) -----
template<int K>
__device__ __forceinline__ void conv4(const float (*s)[72], const float2* __restrict__ wps,
                                      int rq, int cq, float4 out[4]) {
    const int hoff = 4 - K/2;
    const int base_r = 4*rq + 3 - K/2;
    const int xb = 4*cq;

    ull accA[4], accB[4];
#pragma unroll
    for (int c = 0; c < 4; ++c) { accA[c] = 0ULL; accB[c] = 0ULL; }

    float P[12], Cr[12];
    {
        float4 a = *(const float4*)&s[base_r][xb];
        float4 b = *(const float4*)&s[base_r][xb+4];
        float4 c = *(const float4*)&s[base_r][xb+8];
        P[0]=a.x;P[1]=a.y;P[2]=a.z;P[3]=a.w;P[4]=b.x;P[5]=b.y;P[6]=b.z;P[7]=b.w;
        P[8]=c.x;P[9]=c.y;P[10]=c.z;P[11]=c.w;
    }
#pragma unroll
    for (int m = 1; m <= K+2; ++m) {
        {
            float4 a = *(const float4*)&s[base_r+m][xb];
            float4 b = *(const float4*)&s[base_r+m][xb+4];
            float4 c = *(const float4*)&s[base_r+m][xb+8];
            Cr[0]=a.x;Cr[1]=a.y;Cr[2]=a.z;Cr[3]=a.w;Cr[4]=b.x;Cr[5]=b.y;Cr[6]=b.z;Cr[7]=b.w;
            Cr[8]=c.x;Cr[9]=c.y;Cr[10]=c.z;Cr[11]=c.w;
        }
        ull pv[K+3];
#pragma unroll
        for (int i = 0; i < K+3; ++i) pv[i] = pk2(P[hoff+i], Cr[hoff+i]);
        const int mp = m - 1;
        if (mp <= K-1) {
#pragma unroll
            for (int dx = 0; dx < K; ++dx) {
                ull wp = *(const ull*)&wps[mp*K + dx];
#pragma unroll
                for (int c = 0; c < 4; ++c) fma2(accA[c], wp, pv[dx+c]);
            }
        }
        if (mp >= 2) {
#pragma unroll
            for (int dx = 0; dx < K; ++dx) {
                ull wp = *(const ull*)&wps[(mp-2)*K + dx];
#pragma unroll
                for (int c = 0; c < 4; ++c) fma2(accB[c], wp, pv[dx+c]);
            }
        }
#pragma unroll
        for (int i = 0; i < 12; ++i) P[i] = Cr[i];
    }
    float2 a0 = unpk2(accA[0]), a1 = unpk2(accA[1]), a2 = unpk2(accA[2]), a3 = unpk2(accA[3]);
    float2 b0 = unpk2(accB[0]), b1 = unpk2(accB[1]), b2 = unpk2(accB[2]), b3 = unpk2(accB[3]);
    out[0] = make_float4(a0.x, a1.x, a2.x, a3.x);
    out[1] = make_float4(a0.y, a1.y, a2.y, a3.y);
    out[2] = make_float4(b0.x, b1.x, b2.x, b3.x);
    out[3] = make_float4(b0.y, b1.y, b2.y, b3.y);
}

__global__ __launch_bounds__(256)
void k1_dwconv_pool(const float* __restrict__ x, const float* __restrict__ y,
                    const float* __restrict__ h1w3, const float* __restrict__ h1w5,
                    const float* __restrict__ h1w7,
                    const float* __restrict__ h2w3, const float* __restrict__ h2w5,
                    const float* __restrict__ h2w7) {
    __shared__ float s[70][72];
    __shared__ float2 wps[49];

    const int c = blockIdx.y;
    const int z = blockIdx.z;
    const int b = z >> 1;
    const int which = z & 1;
    const int ty0 = (blockIdx.x >> 2) * 64;
    const int tx0 = (blockIdx.x & 3) * 64;
    const int tid = threadIdx.x;

    const float* src = which ? y : x;
    const float* w3  = which ? h2w3 : h1w3;
    const float* w5  = which ? h2w5 : h1w5;
    const float* w7  = which ? h2w7 : h1w7;
    float* dst  = which ? g_yh : g_xh;
    float* pdst = which ? g_py : g_px;

    const float* wp; int wn;
    if (c < 32)      { wp = w3 + c*9;        wn = 9;  }
    else if (c < 48) { wp = w5 + (c-32)*25;  wn = 25; }
    else             { wp = w7 + (c-48)*49;  wn = 49; }
    if (tid < wn) { float w = wp[tid]; wps[tid] = make_float2(w, w); }

    const float* base = src + (size_t)(b*C64 + c) * HW_;
    for (int i = tid; i < 70*18; i += 256) {
        int r = i / 18, q = i - r*18;
        int gy = ty0 - 3 + r, gx = tx0 - 4 + q*4;
        float4 v = make_float4(0.f, 0.f, 0.f, 0.f);
        if ((unsigned)gy < 256u && (unsigned)gx <= 252u)
            v = *(const float4*)&base[gy*W_ + gx];
        *(float4*)&s[r][q*4] = v;
    }
    __syncthreads();

    const int rq = tid >> 4;
    const int cq = tid & 15;
    float4 o[4];
    if (c < 32)      conv4<3>(s, wps, rq, cq, o);
    else if (c < 48) conv4<5>(s, wps, rq, cq, o);
    else             conv4<7>(s, wps, rq, cq, o);

    float* dplane = dst + (size_t)(b*C64 + c) * HW_;
#pragma unroll
    for (int t = 0; t < 4; ++t)
        *(float4*)&dplane[(ty0 + 4*rq + t)*W_ + tx0 + 4*cq] = o[t];

    {
        const int pr  = tid >> 3;
        const int pc4 = (tid & 7) * 4;
        float4 pv;
        float* e = &pv.x;
#pragma unroll
        for (int d = 0; d < 4; ++d) {
            int pc = pc4 + d;
            e[d] = 0.25f * (s[2*pr+3][2*pc+4] + s[2*pr+3][2*pc+5] +
                            s[2*pr+4][2*pc+4] + s[2*pr+4][2*pc+5]);
        }
        float* pplane = pdst + (size_t)(b*C64 + c) * PHW_;
        *(float4*)&pplane[(ty0/2 + pr)*PW_ + tx0/2 + pc4] = pv;
    }
}

// ---------------- K2 merged: Pxx, Pyy, Pxy in one pass (R9 measured, 61 us) ------------
__global__ __launch_bounds__(256, 1)
void k2_moments() {
    extern __shared__ float sm[];
    float* sx = sm;               // [64][130]
    float* sy = sm + 64*130;
    const int b = blockIdx.y;
    const int tid = threadIdx.x;
    const int q = tid >> 4;
    const int l = tid & 15;
    ull axx[16], ayy[16], axy[16];
#pragma unroll
    for (int u = 0; u < 16; ++u) { axx[u] = 0ULL; ayy[u] = 0ULL; axy[u] = 0ULL; }

    for (int chunk = blockIdx.x; chunk < PHW_/128; chunk += gridDim.x) {
        const int n0 = chunk * 128;
        __syncthreads();
        for (int li = tid; li < 2048; li += 256) {
            int cc = li >> 5, t4 = (li & 31) * 4;
            size_t go = ((size_t)(b*C64 + cc) << 14) + n0 + t4;
            float4 vx = *(const float4*)&g_px[go];
            float4 vy = *(const float4*)&g_py[go];
            *(float2*)&sx[cc*130 + t4]     = make_float2(vx.x, vx.y);
            *(float2*)&sx[cc*130 + t4 + 2] = make_float2(vx.z, vx.w);
            *(float2*)&sy[cc*130 + t4]     = make_float2(vy.x, vy.y);
            *(float2*)&sy[cc*130 + t4 + 2] = make_float2(vy.z, vy.w);
        }
        __syncthreads();
#pragma unroll 2
        for (int t = 0; t < 128; t += 2) {
            ull ax[4], bx[4], ay[4], by[4];
#pragma unroll
            for (int u = 0; u < 4; ++u) {
                ax[u] = *(const ull*)&sx[(q + 16*u)*130 + t];
                bx[u] = *(const ull*)&sx[(l + 16*u)*130 + t];
                ay[u] = *(const ull*)&sy[(q + 16*u)*130 + t];
                by[u] = *(const ull*)&sy[(l + 16*u)*130 + t];
            }
#pragma unroll
            for (int u = 0; u < 4; ++u)
#pragma unroll
                for (int v = 0; v < 4; ++v) {
                    fma2(axx[u*4+v], ax[u], bx[v]);
                    fma2(ayy[u*4+v], ay[u], by[v]);
                    fma2(axy[u*4+v], ax[u], by[v]);
                }
        }
    }
#pragma unroll
    for (int u = 0; u < 4; ++u)
#pragma unroll
        for (int v = 0; v < 4; ++v) {
            float2 fx = unpk2(axx[u*4+v]);
            float2 fy = unpk2(ayy[u*4+v]);
            float2 fz = unpk2(axy[u*4+v]);
            int o = b*4096 + (q+16*u)*64 + (l+16*v);
            atomicAdd(&g_Pxx[o], fx.x + fx.y);
            atomicAdd(&g_Pyy[o], fy.x + fy.y);
            atomicAdd(&g_Pxy[o], fz.x + fz.y);
        }
}

// ---------------- K3: Cxy = x_h @ y_h^T, 4x4 tiles, register double-buffered (R5) ------
__global__ __launch_bounds__(256, 2)
void k3_cxy() {
    extern __shared__ float sm[];
    float* sx = sm;               // [64][130]
    float* sy = sm + 64*130;
    const int b = blockIdx.y;
    const int tid = threadIdx.x;
    const int q = tid >> 4;
    const int l = tid & 15;
    const int cc0 = tid >> 5;
    const int t4  = (tid & 31) * 4;
    ull acc[16];
#pragma unroll
    for (int u = 0; u < 16; ++u) acc[u] = 0ULL;

    const int NCH = HW_/128;
    float4 rx[4], ry[4];
    int chunk = blockIdx.x;
    {
        int n0 = chunk * 128;
#pragma unroll
        for (int k = 0; k < 4; ++k) {
            size_t go = ((size_t)(b*C64 + cc0 + 8*k) << 16) + n0 + t4;
            rx[k] = *(const float4*)&g_xh[go];
            ry[k] = *(const float4*)&g_yh[go];
        }
    }
    while (true) {
        __syncthreads();
#pragma unroll
        for (int k = 0; k < 4; ++k) {
            int cc = cc0 + 8*k;
            *(float2*)&sx[cc*130 + t4]     = make_float2(rx[k].x, rx[k].y);
            *(float2*)&sx[cc*130 + t4 + 2] = make_float2(rx[k].z, rx[k].w);
            *(float2*)&sy[cc*130 + t4]     = make_float2(ry[k].x, ry[k].y);
            *(float2*)&sy[cc*130 + t4 + 2] = make_float2(ry[k].z, ry[k].w);
        }
        __syncthreads();
        const int next = chunk + gridDim.x;
        if (next < NCH) {
            int n0 = next * 128;
#pragma unroll
            for (int k = 0; k < 4; ++k) {
                size_t go = ((size_t)(b*C64 + cc0 + 8*k) << 16) + n0 + t4;
                rx[k] = *(const float4*)&g_xh[go];
                ry[k] = *(const float4*)&g_yh[go];
            }
        }
#pragma unroll 4
        for (int t = 0; t < 128; t += 2) {
            ull ax[4], by[4];
#pragma unroll
            for (int u = 0; u < 4; ++u) {
                ax[u] = *(const ull*)&sx[(q + 16*u)*130 + t];
                by[u] = *(const ull*)&sy[(l + 16*u)*130 + t];
            }
#pragma unroll
            for (int u = 0; u < 4; ++u)
#pragma unroll
                for (int v = 0; v < 4; ++v)
                    fma2(acc[u*4+v], ax[u], by[v]);
        }
        if (next >= NCH) break;
        chunk = next;
    }
#pragma unroll
    for (int u = 0; u < 4; ++u)
#pragma unroll
        for (int v = 0; v < 4; ++v) {
            float2 f = unpk2(acc[u*4+v]);
            atomicAdd(&g_Cxy[b*4096 + (q+16*u)*64 + (l+16*v)], f.x + f.y);
        }
}

// ---------------- K4: per-batch finalize, ALL operands staged in smem ------------------
// dynamic smem: 11 matrices x [64][ST] floats (ST=68) = 191,488 B
#define K4_CXY  0
#define K4_PXX  (1*64*ST)
#define K4_PYY  (2*64*ST)
#define K4_PXY  (3*64*ST)
#define K4_KH   (4*64*ST)
#define K4_QL   (5*64*ST)
#define K4_KL   (6*64*ST)
#define K4_VL   (7*64*ST)
#define K4_PROJ (8*64*ST)
#define K4_T2   (9*64*ST)
#define K4_S    (10*64*ST)
#define K4_SMEM ((11*64*ST)*4)

__global__ __launch_bounds__(256)
void k4_finalize(const float* __restrict__ qh, const float* __restrict__ kh,
                 const float* __restrict__ vh, const float* __restrict__ ql,
                 const float* __restrict__ kl, const float* __restrict__ vl,
                 const float* __restrict__ proj,
                 const float* __restrict__ w1, const float* __restrict__ w2,
                 const float* __restrict__ temp) {
    extern __shared__ float dsm[];
    float* sCxy  = dsm + K4_CXY;
    float* sPxx  = dsm + K4_PXX;
    float* sPyy  = dsm + K4_PYY;
    float* sPxy  = dsm + K4_PXY;
    float* skh   = dsm + K4_KH;
    float* sql   = dsm + K4_QL;
    float* skl   = dsm + K4_KL;
    float* svl   = dsm + K4_VL;
    float* sproj = dsm + K4_PROJ;
    float* T2    = dsm + K4_T2;
    float* S     = dsm + K4_S;

    __shared__ float pooled[64], hidden[16], ha[64], nq2[64], nk2[64];
    __shared__ float A[512];
    __shared__ float psum[256];

    const int b = blockIdx.x, tid = threadIdx.x;

    // stage all operand matrices into smem (padded, float4-aligned rows)
    for (int li = tid; li < 1024; li += 256) {
        int r = li >> 4, c4 = (li & 15) * 4;
        int gsrc = r*64 + c4;
        int dstp = r*ST + c4;
        *(float4*)&sCxy[dstp] = *(const float4*)&g_Cxy[b*4096 + gsrc];
        *(float4*)&sPxx[dstp] = *(const float4*)&g_Pxx[b*4096 + gsrc];
        *(float4*)&sPyy[dstp] = *(const float4*)&g_Pyy[b*4096 + gsrc];
        *(float4*)&sPxy[dstp] = *(const float4*)&g_Pxy[b*4096 + gsrc];
        *(float4*)&skh[dstp]  = *(const float4*)&kh[gsrc];
        *(float4*)&sql[dstp]  = *(const float4*)&ql[gsrc];
        *(float4*)&skl[dstp]  = *(const float4*)&kl[gsrc];
        *(float4*)&svl[dstp]  = *(const float4*)&vl[gsrc];
        *(float4*)&sproj[dstp]= *(const float4*)&proj[gsrc];
    }
    __syncthreads();

    {   // pooled[c] = (qh . Cxy . kh^T)[c,c] / HW
        int c = tid & 63, qq = tid >> 6;
        float acc = 0.f;
        for (int i = qq*16; i < qq*16 + 16; ++i) {
            const float* cr = sCxy + i*ST;
            const float* kr = skh + c*ST;
            float s0=0,s1=0,s2=0,s3=0;
            for (int j = 0; j < 64; j += 4) {
                s0 += cr[j  ]*kr[j  ]; s1 += cr[j+1]*kr[j+1];
                s2 += cr[j+2]*kr[j+2]; s3 += cr[j+3]*kr[j+3];
            }
            acc += qh[c*64+i]*(s0+s1+s2+s3);
        }
        psum[tid] = acc;
        __syncthreads();
        if (tid < 64) pooled[tid] = (psum[tid]+psum[tid+64]+psum[tid+128]+psum[tid+192]) * (1.0f/(float)HW_);
        __syncthreads();
    }
    if (tid < 16) {
        float a = 0.f;
        for (int cc = 0; cc < 64; ++cc) a += w1[tid*64+cc]*pooled[cc];
        hidden[tid] = fmaxf(a, 0.f);
    }
    __syncthreads();
    if (tid < 64) {
        float a = 0.f;
        for (int j = 0; j < 16; ++j) a += w2[tid*16+j]*hidden[j];
        ha[tid] = tanhf(a);
    }
    __syncthreads();

    {   // T2 = ql @ Pxy
        int c = tid >> 2, j0 = (tid & 3)*16;
        float acc[16];
#pragma unroll
        for (int v = 0; v < 16; ++v) acc[v] = 0.f;
        for (int i = 0; i < 64; ++i) {
            float a = sql[c*ST+i];
            const float* pr = sPxy + i*ST + j0;
#pragma unroll
            for (int v = 0; v < 16; ++v) acc[v] += a*pr[v];
        }
#pragma unroll
        for (int v = 0; v < 16; ++v) T2[c*ST+j0+v] = acc[v];
    }
    __syncthreads();
    {   // S = T2 @ kl^T
        int c = tid >> 2, d0 = (tid & 3)*16;
        float acc[16];
#pragma unroll
        for (int v = 0; v < 16; ++v) acc[v] = 0.f;
        for (int j = 0; j < 64; ++j) {
            float a = T2[c*ST+j];
#pragma unroll
            for (int v = 0; v < 16; ++v) acc[v] += a*skl[(d0+v)*ST+j];
        }
#pragma unroll
        for (int v = 0; v < 16; ++v) S[c*ST+d0+v] = acc[v];
    }
    __syncthreads();
    {   // T2 = ql @ Pxx -> nq2
        int c = tid >> 2, j0 = (tid & 3)*16;
        float acc[16];
#pragma unroll
        for (int v = 0; v < 16; ++v) acc[v] = 0.f;
        for (int i = 0; i < 64; ++i) {
            float a = sql[c*ST+i];
            const float* pr = sPxx + i*ST + j0;
#pragma unroll
            for (int v = 0; v < 16; ++v) acc[v] += a*pr[v];
        }
#pragma unroll
        for (int v = 0; v < 16; ++v) T2[c*ST+j0+v] = acc[v];
    }
    __syncthreads();
    if (tid < 64) {
        float a = 0.f;
        for (int j = 0; j < 64; ++j) a += T2[tid*ST+j]*sql[tid*ST+j];
        nq2[tid] = a;
    }
    __syncthreads();
    {   // T2 = kl @ Pyy -> nk2
        int c = tid >> 2, j0 = (tid & 3)*16;
        float acc[16];
#pragma unroll
        for (int v = 0; v < 16; ++v) acc[v] = 0.f;
        for (int i = 0; i < 64; ++i) {
            float a = skl[c*ST+i];
            const float* pr = sPyy + i*ST + j0;
#pragma unroll
            for (int v = 0; v < 16; ++v) acc[v] += a*pr[v];
        }
#pragma unroll
        for (int v = 0; v < 16; ++v) T2[c*ST+j0+v] = acc[v];
    }
    __syncthreads();
    if (tid < 64) {
        float a = 0.f;
        for (int j = 0; j < 64; ++j) a += T2[tid*ST+j]*skl[tid*ST+j];
        nk2[tid] = a;
    }
    __syncthreads();

    if (tid < 64) {
        int c = tid, h = c >> 3;
        float dq = fmaxf(sqrtf(nq2[c]), 1e-12f);
        float tt = temp[h];
        float v[8]; float mx = -1e30f;
#pragma unroll
        for (int dd = 0; dd < 8; ++dd) {
            int d = h*8 + dd;
            float dk = fmaxf(sqrtf(nk2[d]), 1e-12f);
            v[dd] = S[c*ST+d] / (dq*dk) * tt;
            mx = fmaxf(mx, v[dd]);
        }
        float sum = 0.f;
#pragma unroll
        for (int dd = 0; dd < 8; ++dd) { v[dd] = expf(v[dd]-mx); sum += v[dd]; }
        float inv = 1.f/sum;
#pragma unroll
        for (int dd = 0; dd < 8; ++dd) A[c*8+dd] = v[dd]*inv;
    }
    __syncthreads();

    {   // S := blockdiag(A) @ vl ; T2 := diag(ha) @ vh
        int c = tid >> 2, i0 = (tid & 3)*16, h = c >> 3;
        float acc[16];
#pragma unroll
        for (int v = 0; v < 16; ++v) acc[v] = 0.f;
#pragma unroll
        for (int dd = 0; dd < 8; ++dd) {
            float a = A[c*8+dd];
            const float* vr = svl + (h*8+dd)*ST + i0;
#pragma unroll
            for (int v = 0; v < 16; ++v) acc[v] += a*vr[v];
        }
#pragma unroll
        for (int v = 0; v < 16; ++v) S[c*ST+i0+v] = acc[v];
        float hac = ha[c];
#pragma unroll
        for (int v = 0; v < 16; ++v) T2[c*ST+i0+v] = hac*vh[c*64+i0+v];
    }
    __syncthreads();

    {   // M1 = proj @ T2 ; M2 = proj @ S
        int o = tid >> 2, i0 = (tid & 3)*16;
        float a1[16], a2[16];
#pragma unroll
        for (int v = 0; v < 16; ++v) { a1[v] = 0.f; a2[v] = 0.f; }
        for (int c = 0; c < 64; ++c) {
            float p = sproj[o*ST+c];
            const float* u  = T2 + c*ST + i0;
            const float* bm = S  + c*ST + i0;
#pragma unroll
            for (int v = 0; v < 16; ++v) { a1[v] += p*u[v]; a2[v] += p*bm[v]; }
        }
#pragma unroll
        for (int v = 0; v < 16; ++v) {
            g_M1[b*4096 + o*64 + i0 + v] = a1[v];
            g_M2[b*4096 + o*64 + i0 + v] = a2[v];
        }
    }

    // re-zero this batch's accumulators for the next graph replay
    {
        float4 z = make_float4(0.f, 0.f, 0.f, 0.f);
#pragma unroll
        for (int t = 0; t < 4; ++t) {
            int off = b*4096 + tid*16 + t*4;
            *(float4*)&g_Cxy[off] = z;
            *(float4*)&g_Pxx[off] = z;
            *(float4*)&g_Pyy[off] = z;
            *(float4*)&g_Pxy[off] = z;
        }
    }
}

// ---------------- K5: out = M1 @ x_h + M2 @ y, 4x4 conflict-free (R4/R9 measured) ------
__global__ __launch_bounds__(256, 2)
void k5_final(const float* __restrict__ y, float* __restrict__ out) {
    extern __shared__ float sm[];
    float* m1 = sm;                 // [64][65]
    float* m2 = sm + 64*65;
    float* sa = sm + 2*64*65;       // x_h chunk [64][132]
    float* sb = sa + 64*132;        // y   chunk [64][132]

    const int b = blockIdx.y;
    const int tid = threadIdx.x;
    const int n0 = blockIdx.x * 128;

    for (int li = tid; li < 4096; li += 256) {
        int o = li >> 6, k = li & 63;
        m1[o*65+k] = g_M1[b*4096 + li];
        m2[o*65+k] = g_M2[b*4096 + li];
    }
    for (int li = tid; li < 2048; li += 256) {
        int cc = li >> 5, t4 = (li & 31) * 4;
        size_t go = ((size_t)(b*C64 + cc) << 16) + n0 + t4;
        *(float4*)&sa[cc*132 + t4] = *(const float4*)&g_xh[go];
        *(float4*)&sb[cc*132 + t4] = *(const float4*)&y[go];
    }
    __syncthreads();

    const int o0 = (tid >> 4) * 4;
    const int l  = tid & 15;
    ull acc[4][4];
#pragma unroll
    for (int u = 0; u < 4; ++u)
#pragma unroll
        for (int v = 0; v < 4; ++v) acc[u][v] = 0ULL;

#pragma unroll 4
    for (int k = 0; k < 64; ++k) {
        ull a1p[4], a2p[4];
#pragma unroll
        for (int u = 0; u < 4; ++u) {
            float a1 = m1[(o0+u)*65 + k];
            float a2 = m2[(o0+u)*65 + k];
            a1p[u] = pk2(a1, a1);
            a2p[u] = pk2(a2, a2);
        }
        ull bx[4], by[4];
#pragma unroll
        for (int v = 0; v < 4; ++v) {
            bx[v] = *(const ull*)&sa[k*132 + 2*l + 32*v];
            by[v] = *(const ull*)&sb[k*132 + 2*l + 32*v];
        }
#pragma unroll
        for (int u = 0; u < 4; ++u)
#pragma unroll
            for (int v = 0; v < 4; ++v) {
                fma2(acc[u][v], a1p[u], bx[v]);
                fma2(acc[u][v], a2p[u], by[v]);
            }
    }
#pragma unroll
    for (int u = 0; u < 4; ++u) {
        float* op = out + (size_t)(b*C64 + o0 + u)*HW_ + n0 + 2*l;
#pragma unroll
        for (int v = 0; v < 4; ++v) {
            float2 f = unpk2(acc[u][v]);
            *(float2*)(op + 32*v) = f;
        }
    }
}

// ---------------- launcher ----------------
extern "C" void kernel_launch(void* const* d_in, const int* in_sizes, int n_in,
                              void* d_out, int out_size) {
    (void)in_sizes; (void)n_in; (void)out_size;
    const float* x      = (const float*)d_in[0];
    const float* y      = (const float*)d_in[1];
    const float* h1w3   = (const float*)d_in[2];
    const float* h1w5   = (const float*)d_in[3];
    const float* h1w7   = (const float*)d_in[4];
    const float* h2w3   = (const float*)d_in[5];
    const float* h2w5   = (const float*)d_in[6];
    const float* h2w7   = (const float*)d_in[7];
    const float* qh_w   = (const float*)d_in[8];
    const float* kh_w   = (const float*)d_in[9];
    const float* vh_w   = (const float*)d_in[10];
    const float* ql_w   = (const float*)d_in[11];
    const float* kl_w   = (const float*)d_in[12];
    const float* vl_w   = (const float*)d_in[13];
    const float* proj_w = (const float*)d_in[14];
    const float* w1     = (const float*)d_in[15];
    const float* w2     = (const float*)d_in[16];
    const float* temp   = (const float*)d_in[17];
    float* out = (float*)d_out;

    const int SMEM_GEMM = 2*64*130*4;               // 66560
    const int SMEM5     = (2*64*65 + 2*64*132)*4;   // 100864
    cudaFuncSetAttribute(k3_cxy,      cudaFuncAttributeMaxDynamicSharedMemorySize, SMEM_GEMM);
    cudaFuncSetAttribute(k2_moments,  cudaFuncAttributeMaxDynamicSharedMemorySize, SMEM_GEMM);
    cudaFuncSetAttribute(k4_finalize, cudaFuncAttributeMaxDynamicSharedMemorySize, K4_SMEM);
    cudaFuncSetAttribute(k5_final,    cudaFuncAttributeMaxDynamicSharedMemorySize, SMEM5);

    // order: k1(0), k2(1), k3(2), k4(3) <- ncu profiles launch index 3, k5(4)
    k1_dwconv_pool<<<dim3(16, 64, 8), 256>>>(x, y, h1w3, h1w5, h1w7, h2w3, h2w5, h2w7);
    k2_moments<<<dim3(37, B_), 256, SMEM_GEMM>>>();
    k3_cxy<<<dim3(74, B_), 256, SMEM_GEMM>>>();
    k4_finalize<<<B_, 256, K4_SMEM>>>(qh_w, kh_w, vh_w, ql_w, kl_w, vl_w, proj_w, w1, w2, temp);
    k5_final<<<dim3(HW_/128, B_), 256, SMEM5>>>(y, out);
}